// round 1
// baseline (speedup 1.0000x reference)
#include <cuda_runtime.h>
#include <math.h>

#define BB 4
#define TT 1024
#define SS 1024
#define DD 1024
#define HH 16
#define DKD 64
#define DFFN 4096
#define LN_EPS 1e-6f

// ---------------- scratch (no allocations allowed) ----------------
__device__ float g_q [BB*TT*DD];
__device__ float g_k [BB*TT*DD];
__device__ float g_v [BB*TT*DD];
__device__ float g_t0[BB*TT*DD];
__device__ float g_t1[BB*TT*DD];
__device__ float g_x1[BB*TT*DD];
__device__ float g_x2[BB*TT*DD];
__device__ float g_ff[BB*TT*DFFN];

// ---------------- SGEMM: C[M,N] = A[M,K] @ W[K,N] + bias, optional relu ----
// 128x128 tile, BK=16, 256 threads, 8x8 per thread.
__global__ __launch_bounds__(256) void sgemm_bias(
    const float* __restrict__ A, const float* __restrict__ W,
    const float* __restrict__ bias, float* __restrict__ C,
    int M, int N, int K, int relu)
{
    __shared__ float As[16][128];
    __shared__ float Ws[16][128];
    const int tid = threadIdx.x;
    const int bx = blockIdx.x, by = blockIdx.y;
    const int tx = tid & 15, ty = tid >> 4;

    const float* Ab = A + (size_t)by * 128 * K;
    const float* Wb = W + (size_t)bx * 128;

    float acc[8][8];
    #pragma unroll
    for (int i = 0; i < 8; i++)
        #pragma unroll
        for (int j = 0; j < 8; j++) acc[i][j] = 0.f;

    const int aRow = tid >> 2, aCol = (tid & 3) << 2;
    const int wRow = tid >> 5, wCol = (tid & 31) << 2;

    for (int k0 = 0; k0 < K; k0 += 16) {
        #pragma unroll
        for (int i = 0; i < 2; i++) {
            int r = aRow + i * 64;
            float4 v = *(const float4*)(Ab + (size_t)r * K + k0 + aCol);
            As[aCol + 0][r] = v.x; As[aCol + 1][r] = v.y;
            As[aCol + 2][r] = v.z; As[aCol + 3][r] = v.w;
        }
        #pragma unroll
        for (int i = 0; i < 2; i++) {
            int r = wRow + i * 8;
            *(float4*)&Ws[r][wCol] = *(const float4*)(Wb + (size_t)(k0 + r) * N + wCol);
        }
        __syncthreads();
        #pragma unroll
        for (int kk = 0; kk < 16; kk++) {
            float a[8], w[8];
            *(float4*)&a[0] = *(float4*)&As[kk][ty * 8];
            *(float4*)&a[4] = *(float4*)&As[kk][ty * 8 + 4];
            *(float4*)&w[0] = *(float4*)&Ws[kk][tx * 8];
            *(float4*)&w[4] = *(float4*)&Ws[kk][tx * 8 + 4];
            #pragma unroll
            for (int i = 0; i < 8; i++)
                #pragma unroll
                for (int j = 0; j < 8; j++)
                    acc[i][j] += a[i] * w[j];
        }
        __syncthreads();
    }

    #pragma unroll
    for (int i = 0; i < 8; i++) {
        int row = by * 128 + ty * 8 + i;
        #pragma unroll
        for (int j = 0; j < 8; j += 4) {
            int col = bx * 128 + tx * 8 + j;
            float4 b4 = *(const float4*)(bias + col);
            float4 o;
            o.x = acc[i][j + 0] + b4.x;
            o.y = acc[i][j + 1] + b4.y;
            o.z = acc[i][j + 2] + b4.z;
            o.w = acc[i][j + 3] + b4.w;
            if (relu) {
                o.x = fmaxf(o.x, 0.f); o.y = fmaxf(o.y, 0.f);
                o.z = fmaxf(o.z, 0.f); o.w = fmaxf(o.w, 0.f);
            }
            *(float4*)(C + (size_t)row * N + col) = o;
        }
    }
}

// ---------------- attention scores: S[z,q,k] = (Q_z[q,:] . K_z[k,:]) / 8 ----
// Q,K layout: [B*T, D] where head h occupies cols [h*64, h*64+64).
// grid: (k_tiles=16, q_tiles=16, z=B*H), block 256, 64x64 tile, 4x4/thread.
// Causal: tiles with k0 > q0 are fully masked -> skipped (softmax overwrites).
__global__ __launch_bounds__(256) void attn_scores(
    const float* __restrict__ Q, const float* __restrict__ Kv,
    float* __restrict__ Sc, int causal)
{
    const int z = blockIdx.z;
    const int b = z >> 4, h = z & 15;
    const int q0 = blockIdx.y * 64, k0 = blockIdx.x * 64;
    if (causal && k0 > q0) return;

    __shared__ float Qs[64][65];
    __shared__ float Ks[64][65];
    const int tid = threadIdx.x;
    const float* Qb = Q  + ((size_t)(b * TT + q0)) * DD + h * DKD;
    const float* Kb = Kv + ((size_t)(b * TT + k0)) * DD + h * DKD;

    #pragma unroll
    for (int it = 0; it < 4; it++) {
        int f = tid + it * 256;
        int r = f >> 4, c = (f & 15) << 2;
        float4 qv = *(const float4*)(Qb + (size_t)r * DD + c);
        Qs[r][c] = qv.x; Qs[r][c + 1] = qv.y; Qs[r][c + 2] = qv.z; Qs[r][c + 3] = qv.w;
        float4 kv = *(const float4*)(Kb + (size_t)r * DD + c);
        Ks[r][c] = kv.x; Ks[r][c + 1] = kv.y; Ks[r][c + 2] = kv.z; Ks[r][c + 3] = kv.w;
    }
    __syncthreads();

    const int tx = tid & 15, ty = tid >> 4;
    float acc[4][4];
    #pragma unroll
    for (int i = 0; i < 4; i++)
        #pragma unroll
        for (int j = 0; j < 4; j++) acc[i][j] = 0.f;

    #pragma unroll
    for (int kk = 0; kk < 64; kk++) {
        float a[4], bb[4];
        #pragma unroll
        for (int i = 0; i < 4; i++) a[i]  = Qs[ty * 4 + i][kk];
        #pragma unroll
        for (int j = 0; j < 4; j++) bb[j] = Ks[tx * 4 + j][kk];
        #pragma unroll
        for (int i = 0; i < 4; i++)
            #pragma unroll
            for (int j = 0; j < 4; j++)
                acc[i][j] += a[i] * bb[j];
    }

    float* Out = Sc + ((size_t)z * TT + q0) * TT + k0;
    #pragma unroll
    for (int i = 0; i < 4; i++)
        #pragma unroll
        for (int j = 0; j < 4; j++)
            Out[(size_t)(ty * 4 + i) * TT + tx * 4 + j] = acc[i][j] * 0.125f;
}

// ---------------- softmax with mask, in place on the score/output buffer ----
// grid (T, B*H), 256 threads, 4 elements/thread. mode 0: tgt_mask[q*T+k],
// mode 1: src_mask[b*S+k]. Masked -> -1e9 before max/exp (matches reference).
__global__ __launch_bounds__(256) void softmax_mask(
    float* __restrict__ Sc, const int* __restrict__ mask, int mode)
{
    const int q = blockIdx.x, z = blockIdx.y;
    const int b = z >> 4;
    float* row = Sc + ((size_t)z * TT + q) * TT;
    const int tid = threadIdx.x;

    float v[4];
    float mx = -3.0e38f;
    #pragma unroll
    for (int i = 0; i < 4; i++) {
        int k = tid + i * 256;
        float s = row[k];
        int mv = (mode == 0) ? mask[q * TT + k] : mask[b * SS + k];
        v[i] = (mv == 0) ? -1e9f : s;
        mx = fmaxf(mx, v[i]);
    }

    __shared__ float red[8];
    __shared__ float red2[8];
    #pragma unroll
    for (int o = 16; o > 0; o >>= 1) mx = fmaxf(mx, __shfl_xor_sync(0xffffffffu, mx, o));
    if ((tid & 31) == 0) red[tid >> 5] = mx;
    __syncthreads();
    mx = red[0];
    #pragma unroll
    for (int w = 1; w < 8; w++) mx = fmaxf(mx, red[w]);

    float sum = 0.f;
    #pragma unroll
    for (int i = 0; i < 4; i++) { v[i] = __expf(v[i] - mx); sum += v[i]; }
    #pragma unroll
    for (int o = 16; o > 0; o >>= 1) sum += __shfl_xor_sync(0xffffffffu, sum, o);
    if ((tid & 31) == 0) red2[tid >> 5] = sum;
    __syncthreads();
    sum = 0.f;
    #pragma unroll
    for (int w = 0; w < 8; w++) sum += red2[w];
    float inv = 1.0f / sum;
    #pragma unroll
    for (int i = 0; i < 4; i++) row[tid + i * 256] = v[i] * inv;
}

// ---------------- attn @ V: O[b,q,h,:] = sum_k P[z,q,k] * V[b,k,h,:] --------
// grid (q_tiles=16, z=B*H), 64 q-rows x 64 dk per block, 4x4/thread.
// Causal: P is exactly zero for k > q, so truncate k-loop at q0+64.
__global__ __launch_bounds__(256) void attn_av(
    const float* __restrict__ P, const float* __restrict__ V,
    float* __restrict__ O, int causal)
{
    const int z = blockIdx.y, b = z >> 4, h = z & 15;
    const int q0 = blockIdx.x * 64;
    __shared__ float  Ps[64][65];
    __shared__ float4 Vs[64][16];
    const int tid = threadIdx.x;
    const int tx = tid & 15, ty = tid >> 4;

    float acc[4][4];
    #pragma unroll
    for (int i = 0; i < 4; i++)
        #pragma unroll
        for (int j = 0; j < 4; j++) acc[i][j] = 0.f;

    const int kend = causal ? (q0 + 64) : TT;
    for (int k0 = 0; k0 < kend; k0 += 64) {
        const float* Pb = P + ((size_t)z * TT + q0) * TT + k0;
        const float* Vb = V + ((size_t)(b * TT + k0)) * DD + h * DKD;
        #pragma unroll
        for (int it = 0; it < 4; it++) {
            int f = tid + it * 256;
            int r = f >> 4, c = (f & 15) << 2;
            float4 pv = *(const float4*)(Pb + (size_t)r * TT + c);
            Ps[r][c] = pv.x; Ps[r][c + 1] = pv.y; Ps[r][c + 2] = pv.z; Ps[r][c + 3] = pv.w;
            Vs[r][f & 15] = *(const float4*)(Vb + (size_t)r * DD + c);
        }
        __syncthreads();
        #pragma unroll
        for (int kk = 0; kk < 64; kk++) {
            float a[4];
            #pragma unroll
            for (int i = 0; i < 4; i++) a[i] = Ps[ty * 4 + i][kk];
            float4 w4 = Vs[kk][tx];
            acc[0][0] += a[0] * w4.x; acc[0][1] += a[0] * w4.y; acc[0][2] += a[0] * w4.z; acc[0][3] += a[0] * w4.w;
            acc[1][0] += a[1] * w4.x; acc[1][1] += a[1] * w4.y; acc[1][2] += a[1] * w4.z; acc[1][3] += a[1] * w4.w;
            acc[2][0] += a[2] * w4.x; acc[2][1] += a[2] * w4.y; acc[2][2] += a[2] * w4.z; acc[2][3] += a[2] * w4.w;
            acc[3][0] += a[3] * w4.x; acc[3][1] += a[3] * w4.y; acc[3][2] += a[3] * w4.z; acc[3][3] += a[3] * w4.w;
        }
        __syncthreads();
    }

    float* Ob = O + ((size_t)(b * TT + q0)) * DD + h * DKD;
    #pragma unroll
    for (int i = 0; i < 4; i++) {
        float4 o = make_float4(acc[i][0], acc[i][1], acc[i][2], acc[i][3]);
        *(float4*)(Ob + (size_t)(ty * 4 + i) * DD + tx * 4) = o;
    }
}

// ---------------- residual add + LayerNorm (ddof=1, eps added to std) -------
// grid (B*T), 256 threads, row of 1024.
__global__ __launch_bounds__(256) void add_ln(
    const float* __restrict__ X, const float* __restrict__ Dl,
    const float* __restrict__ g, const float* __restrict__ be,
    float* __restrict__ O)
{
    const int row = blockIdx.x;
    const float* x  = X  + (size_t)row * DD;
    const float* dl = Dl + (size_t)row * DD;
    const int tid = threadIdx.x;

    float v[4];
    float s = 0.f;
    #pragma unroll
    for (int i = 0; i < 4; i++) {
        int c = tid + i * 256;
        v[i] = x[c] + dl[c];
        s += v[i];
    }
    __shared__ float red[8];
    #pragma unroll
    for (int o = 16; o > 0; o >>= 1) s += __shfl_xor_sync(0xffffffffu, s, o);
    if ((tid & 31) == 0) red[tid >> 5] = s;
    __syncthreads();
    s = 0.f;
    #pragma unroll
    for (int w = 0; w < 8; w++) s += red[w];
    float mean = s * (1.0f / 1024.0f);

    float qq = 0.f;
    #pragma unroll
    for (int i = 0; i < 4; i++) { float d = v[i] - mean; qq += d * d; }
    __syncthreads();
    #pragma unroll
    for (int o = 16; o > 0; o >>= 1) qq += __shfl_xor_sync(0xffffffffu, qq, o);
    if ((tid & 31) == 0) red[tid >> 5] = qq;
    __syncthreads();
    qq = 0.f;
    #pragma unroll
    for (int w = 0; w < 8; w++) qq += red[w];

    float stdv = sqrtf(qq * (1.0f / 1023.0f));
    float inv = 1.0f / (stdv + LN_EPS);
    #pragma unroll
    for (int i = 0; i < 4; i++) {
        int c = tid + i * 256;
        O[(size_t)row * DD + c] = g[c] * (v[i] - mean) * inv + be[c];
    }
}

// ---------------- orchestration ----------------
extern "C" void kernel_launch(void* const* d_in, const int* in_sizes, int n_in,
                              void* d_out, int out_size)
{
    const float* x        = (const float*)d_in[0];
    const float* enc      = (const float*)d_in[1];
    const int*   src_mask = (const int*)  d_in[2];
    const int*   tgt_mask = (const int*)  d_in[3];
    const float* wq_s = (const float*)d_in[4],  *bq_s = (const float*)d_in[5];
    const float* wk_s = (const float*)d_in[6],  *bk_s = (const float*)d_in[7];
    const float* wv_s = (const float*)d_in[8],  *bv_s = (const float*)d_in[9];
    const float* wo_s = (const float*)d_in[10], *bo_s = (const float*)d_in[11];
    const float* wq_c = (const float*)d_in[12], *bq_c = (const float*)d_in[13];
    const float* wk_c = (const float*)d_in[14], *bk_c = (const float*)d_in[15];
    const float* wv_c = (const float*)d_in[16], *bv_c = (const float*)d_in[17];
    const float* wo_c = (const float*)d_in[18], *bo_c = (const float*)d_in[19];
    const float* w1   = (const float*)d_in[20], *b1   = (const float*)d_in[21];
    const float* w2   = (const float*)d_in[22], *b2   = (const float*)d_in[23];
    const float* g1   = (const float*)d_in[24], *be1  = (const float*)d_in[25];
    const float* g2   = (const float*)d_in[26], *be2  = (const float*)d_in[27];
    const float* g3   = (const float*)d_in[28], *be3  = (const float*)d_in[29];

    float* out     = (float*)d_out;
    float* self_w  = out + (size_t)BB * TT * DD;
    float* cross_w = self_w + (size_t)BB * HH * TT * TT;

    float *Q, *K, *V, *T0, *T1, *X1, *X2, *FF;
    cudaGetSymbolAddress((void**)&Q,  g_q);
    cudaGetSymbolAddress((void**)&K,  g_k);
    cudaGetSymbolAddress((void**)&V,  g_v);
    cudaGetSymbolAddress((void**)&T0, g_t0);
    cudaGetSymbolAddress((void**)&T1, g_t1);
    cudaGetSymbolAddress((void**)&X1, g_x1);
    cudaGetSymbolAddress((void**)&X2, g_x2);
    cudaGetSymbolAddress((void**)&FF, g_ff);

    const int M = BB * TT;                 // 4096
    dim3 blk(256);
    dim3 gemmD(DD / 128, M / 128);         // N=1024
    dim3 gemmF(DFFN / 128, M / 128);       // N=4096
    dim3 scoreG(TT / 64, TT / 64, BB * HH);
    dim3 smaxG(TT, BB * HH);
    dim3 avG(TT / 64, BB * HH);
    dim3 lnG(M);

    // ---- self attention ----
    sgemm_bias<<<gemmD, blk>>>(x, wq_s, bq_s, Q, M, DD, DD, 0);
    sgemm_bias<<<gemmD, blk>>>(x, wk_s, bk_s, K, M, DD, DD, 0);
    sgemm_bias<<<gemmD, blk>>>(x, wv_s, bv_s, V, M, DD, DD, 0);
    attn_scores<<<scoreG, blk>>>(Q, K, self_w, 1);
    softmax_mask<<<smaxG, blk>>>(self_w, tgt_mask, 0);
    attn_av<<<avG, blk>>>(self_w, V, T0, 1);
    sgemm_bias<<<gemmD, blk>>>(T0, wo_s, bo_s, T1, M, DD, DD, 0);
    add_ln<<<lnG, blk>>>(x, T1, g1, be1, X1);

    // ---- cross attention ----
    sgemm_bias<<<gemmD, blk>>>(X1, wq_c, bq_c, Q, M, DD, DD, 0);
    sgemm_bias<<<gemmD, blk>>>(enc, wk_c, bk_c, K, M, DD, DD, 0);
    sgemm_bias<<<gemmD, blk>>>(enc, wv_c, bv_c, V, M, DD, DD, 0);
    attn_scores<<<scoreG, blk>>>(Q, K, cross_w, 0);
    softmax_mask<<<smaxG, blk>>>(cross_w, src_mask, 1);
    attn_av<<<avG, blk>>>(cross_w, V, T0, 0);
    sgemm_bias<<<gemmD, blk>>>(T0, wo_c, bo_c, T1, M, DD, DD, 0);
    add_ln<<<lnG, blk>>>(X1, T1, g2, be2, X2);

    // ---- feed-forward ----
    sgemm_bias<<<gemmF, blk>>>(X2, w1, b1, FF, M, DFFN, DD, 1);
    sgemm_bias<<<gemmD, blk>>>(FF, w2, b2, T1, M, DD, DFFN, 0);
    add_ln<<<lnG, blk>>>(X2, T1, g3, be3, out);

    (void)in_sizes; (void)n_in; (void)out_size;
}

// round 3
// speedup vs baseline: 1.4716x; 1.4716x over previous
#include <cuda_runtime.h>
#include <cuda_bf16.h>
#include <math.h>
#include <stdint.h>

#define BB 4
#define TT 1024
#define SS 1024
#define DD 1024
#define HH 16
#define DKD 64
#define DFFN 4096
#define LN_EPS 1e-6f

// ===================== scratch (no allocations) =====================
__device__ float g_q [BB*TT*DD];
__device__ float g_k [BB*TT*DD];
__device__ float g_v [BB*TT*DD];
__device__ float g_t0[BB*TT*DD];
__device__ float g_t1[BB*TT*DD];
__device__ float g_x1[BB*TT*DD];
__device__ float g_x2[BB*TT*DD];
__device__ float g_ff[BB*TT*DFFN];

// bf16 split buffers
__device__ __nv_bfloat16 g_a3 [4096ULL * 3072];         // activations [M, 3K]
__device__ __nv_bfloat16 g_ff3[4096ULL * 12288];        // FF activations [M, 3*4096]
// weights (transposed + split): 8 x [1024,3072] + w1 [4096,3072] + w2 [1024,12288]
#define W3D (1024ULL*3072)
#define W1OFF (8*W3D)
#define W2OFF (8*W3D + 4096ULL*3072)
__device__ __nv_bfloat16 g_wt3[8*W3D + 4096ULL*3072 + 1024ULL*12288];

// ===================== split/convert kernels =====================
// A [M, K] fp32 -> O [M, 3K] bf16 as [hi | lo | hi]
__global__ __launch_bounds__(256) void split_act(
    const float* __restrict__ A, __nv_bfloat16* __restrict__ O, int kbits)
{
    const int K = 1 << kbits;
    size_t idx = (size_t)blockIdx.x * 256 + threadIdx.x;
    size_t base = idx << 2;
    size_t m = base >> kbits;
    int k = (int)(base & (size_t)(K - 1));
    float4 v = *(const float4*)(A + base);
    __nv_bfloat16 h0 = __float2bfloat16(v.x), h1 = __float2bfloat16(v.y);
    __nv_bfloat16 h2 = __float2bfloat16(v.z), h3 = __float2bfloat16(v.w);
    __nv_bfloat16 l0 = __float2bfloat16(v.x - __bfloat162float(h0));
    __nv_bfloat16 l1 = __float2bfloat16(v.y - __bfloat162float(h1));
    __nv_bfloat16 l2 = __float2bfloat16(v.z - __bfloat162float(h2));
    __nv_bfloat16 l3 = __float2bfloat16(v.w - __bfloat162float(h3));
    uint2 hh, ll;
    hh.x = (uint32_t)__bfloat16_as_ushort(h0) | ((uint32_t)__bfloat16_as_ushort(h1) << 16);
    hh.y = (uint32_t)__bfloat16_as_ushort(h2) | ((uint32_t)__bfloat16_as_ushort(h3) << 16);
    ll.x = (uint32_t)__bfloat16_as_ushort(l0) | ((uint32_t)__bfloat16_as_ushort(l1) << 16);
    ll.y = (uint32_t)__bfloat16_as_ushort(l2) | ((uint32_t)__bfloat16_as_ushort(l3) << 16);
    __nv_bfloat16* row = O + m * (size_t)(3 * K);
    *(uint2*)(row + k)         = hh;
    *(uint2*)(row + K + k)     = ll;
    *(uint2*)(row + 2 * K + k) = hh;
}

// W [K, N] fp32 -> O [N, 3K] bf16 as [hi | hi | lo] (transposed)
__global__ void split_w(
    const float* __restrict__ W, __nv_bfloat16* __restrict__ O, int K, int N)
{
    __shared__ float t[32][33];
    int k = blockIdx.y * 32 + threadIdx.y;
    int n = blockIdx.x * 32 + threadIdx.x;
    t[threadIdx.y][threadIdx.x] = W[(size_t)k * N + n];
    __syncthreads();
    int nn = blockIdx.x * 32 + threadIdx.y;
    int kk = blockIdx.y * 32 + threadIdx.x;
    float v = t[threadIdx.x][threadIdx.y];
    __nv_bfloat16 h = __float2bfloat16(v);
    __nv_bfloat16 l = __float2bfloat16(v - __bfloat162float(h));
    size_t ro = (size_t)nn * (size_t)(3 * K);
    O[ro + kk]         = h;
    O[ro + K + kk]     = h;
    O[ro + 2 * K + kk] = l;
}

// ===================== HMMA bf16 GEMM =====================
// C[M,N] = A3[M,K3] @ WT3[N,K3]^T + bias (+relu)
// 128x128 block tile, BK=32 bf16, 8 warps (2m x 4n), warp tile 64x32.
#define PADK 40   // bf16 elems per smem row (80 B) -> conflict-free frags

__device__ __forceinline__ void mma_bf16(
    float* d, const uint32_t* a, const uint32_t* b)
{
    asm volatile(
        "mma.sync.aligned.m16n8k16.row.col.f32.bf16.bf16.f32 "
        "{%0,%1,%2,%3}, {%4,%5,%6,%7}, {%8,%9}, {%0,%1,%2,%3};"
        : "+f"(d[0]), "+f"(d[1]), "+f"(d[2]), "+f"(d[3])
        : "r"(a[0]), "r"(a[1]), "r"(a[2]), "r"(a[3]), "r"(b[0]), "r"(b[1]));
}

__global__ __launch_bounds__(256) void gemm_mma(
    const __nv_bfloat16* __restrict__ A3, const __nv_bfloat16* __restrict__ WT3,
    const float* __restrict__ bias, float* __restrict__ C,
    int N, int K3, int relu)
{
    __shared__ __nv_bfloat16 As[2][128 * PADK];
    __shared__ __nv_bfloat16 Bs[2][128 * PADK];

    const int tid = threadIdx.x;
    const int lane = tid & 31, wid = tid >> 5;
    const int wm = wid >> 2, wn = wid & 3;
    const int grp = lane >> 2, tg = lane & 3;

    const size_t arow0 = (size_t)blockIdx.y * 128;
    const size_t bcol0 = (size_t)blockIdx.x * 128;

    // per-thread global load assignment: 2 segments of 16B each (8 bf16)
    const int seg0 = tid, seg1 = tid + 256;
    const int r0 = seg0 >> 2, s0 = seg0 & 3;
    const int r1 = seg1 >> 2, s1 = seg1 & 3;
    const __nv_bfloat16* pA0 = A3  + (arow0 + r0) * (size_t)K3 + s0 * 8;
    const __nv_bfloat16* pA1 = A3  + (arow0 + r1) * (size_t)K3 + s1 * 8;
    const __nv_bfloat16* pB0 = WT3 + (bcol0 + r0) * (size_t)K3 + s0 * 8;
    const __nv_bfloat16* pB1 = WT3 + (bcol0 + r1) * (size_t)K3 + s1 * 8;
    const int so0 = r0 * PADK + s0 * 8;
    const int so1 = r1 * PADK + s1 * 8;

    float acc[4][4][4];
    #pragma unroll
    for (int i = 0; i < 4; i++)
        #pragma unroll
        for (int j = 0; j < 4; j++)
            #pragma unroll
            for (int q = 0; q < 4; q++) acc[i][j][q] = 0.f;

    const int NC = K3 >> 5;

    // prologue: chunk 0
    uint4 ra0 = *(const uint4*)pA0;
    uint4 ra1 = *(const uint4*)pA1;
    uint4 rb0 = *(const uint4*)pB0;
    uint4 rb1 = *(const uint4*)pB1;
    *(uint4*)&As[0][so0] = ra0;
    *(uint4*)&As[0][so1] = ra1;
    *(uint4*)&Bs[0][so0] = rb0;
    *(uint4*)&Bs[0][so1] = rb1;
    __syncthreads();

    for (int c = 0; c < NC; c++) {
        const int buf = c & 1;
        if (c + 1 < NC) {
            const size_t off = (size_t)(c + 1) * 32;
            ra0 = *(const uint4*)(pA0 + off);
            ra1 = *(const uint4*)(pA1 + off);
            rb0 = *(const uint4*)(pB0 + off);
            rb1 = *(const uint4*)(pB1 + off);
        }
        #pragma unroll
        for (int ks = 0; ks < 2; ks++) {
            const int kb = ks * 16 + tg * 2;
            uint32_t a[4][4], b[4][2];
            #pragma unroll
            for (int ms = 0; ms < 4; ms++) {
                int r = wm * 64 + ms * 16 + grp;
                a[ms][0] = *(const uint32_t*)&As[buf][r * PADK + kb];
                a[ms][1] = *(const uint32_t*)&As[buf][(r + 8) * PADK + kb];
                a[ms][2] = *(const uint32_t*)&As[buf][r * PADK + kb + 8];
                a[ms][3] = *(const uint32_t*)&As[buf][(r + 8) * PADK + kb + 8];
            }
            #pragma unroll
            for (int ns = 0; ns < 4; ns++) {
                int rn = wn * 32 + ns * 8 + grp;
                b[ns][0] = *(const uint32_t*)&Bs[buf][rn * PADK + kb];
                b[ns][1] = *(const uint32_t*)&Bs[buf][rn * PADK + kb + 8];
            }
            #pragma unroll
            for (int ms = 0; ms < 4; ms++)
                #pragma unroll
                for (int ns = 0; ns < 4; ns++)
                    mma_bf16(acc[ms][ns], a[ms], b[ns]);
        }
        if (c + 1 < NC) {
            const int nb = buf ^ 1;
            *(uint4*)&As[nb][so0] = ra0;
            *(uint4*)&As[nb][so1] = ra1;
            *(uint4*)&Bs[nb][so0] = rb0;
            *(uint4*)&Bs[nb][so1] = rb1;
        }
        __syncthreads();
    }

    // epilogue: bias + optional relu, float2 stores
    #pragma unroll
    for (int ms = 0; ms < 4; ms++) {
        const size_t rr0 = arow0 + wm * 64 + ms * 16 + grp;
        #pragma unroll
        for (int ns = 0; ns < 4; ns++) {
            const size_t cc = bcol0 + wn * 32 + ns * 8 + tg * 2;
            float bx = bias[cc], by = bias[cc + 1];
            float v0 = acc[ms][ns][0] + bx;
            float v1 = acc[ms][ns][1] + by;
            float v2 = acc[ms][ns][2] + bx;
            float v3 = acc[ms][ns][3] + by;
            if (relu) {
                v0 = fmaxf(v0, 0.f); v1 = fmaxf(v1, 0.f);
                v2 = fmaxf(v2, 0.f); v3 = fmaxf(v3, 0.f);
            }
            *(float2*)(C + rr0 * N + cc)       = make_float2(v0, v1);
            *(float2*)(C + (rr0 + 8) * N + cc) = make_float2(v2, v3);
        }
    }
}

// ===================== attention scores (SIMT fp32) =====================
__global__ __launch_bounds__(256) void attn_scores(
    const float* __restrict__ Q, const float* __restrict__ Kv,
    float* __restrict__ Sc, int causal)
{
    const int z = blockIdx.z;
    const int b = z >> 4, h = z & 15;
    const int q0 = blockIdx.y * 64, k0 = blockIdx.x * 64;
    if (causal && k0 > q0) return;

    __shared__ float Qs[64][65];
    __shared__ float Ks[64][65];
    const int tid = threadIdx.x;
    const float* Qb = Q  + ((size_t)(b * TT + q0)) * DD + h * DKD;
    const float* Kb = Kv + ((size_t)(b * TT + k0)) * DD + h * DKD;

    #pragma unroll
    for (int it = 0; it < 4; it++) {
        int f = tid + it * 256;
        int r = f >> 4, c = (f & 15) << 2;
        float4 qv = *(const float4*)(Qb + (size_t)r * DD + c);
        Qs[r][c] = qv.x; Qs[r][c + 1] = qv.y; Qs[r][c + 2] = qv.z; Qs[r][c + 3] = qv.w;
        float4 kv = *(const float4*)(Kb + (size_t)r * DD + c);
        Ks[r][c] = kv.x; Ks[r][c + 1] = kv.y; Ks[r][c + 2] = kv.z; Ks[r][c + 3] = kv.w;
    }
    __syncthreads();

    const int tx = tid & 15, ty = tid >> 4;
    float acc[4][4];
    #pragma unroll
    for (int i = 0; i < 4; i++)
        #pragma unroll
        for (int j = 0; j < 4; j++) acc[i][j] = 0.f;

    #pragma unroll
    for (int kk = 0; kk < 64; kk++) {
        float a[4], bb[4];
        #pragma unroll
        for (int i = 0; i < 4; i++) a[i]  = Qs[ty * 4 + i][kk];
        #pragma unroll
        for (int j = 0; j < 4; j++) bb[j] = Ks[tx * 4 + j][kk];
        #pragma unroll
        for (int i = 0; i < 4; i++)
            #pragma unroll
            for (int j = 0; j < 4; j++)
                acc[i][j] += a[i] * bb[j];
    }

    float* Out = Sc + ((size_t)z * TT + q0) * TT + k0;
    #pragma unroll
    for (int i = 0; i < 4; i++)
        #pragma unroll
        for (int j = 0; j < 4; j++)
            Out[(size_t)(ty * 4 + i) * TT + tx * 4 + j] = acc[i][j] * 0.125f;
}

// ===================== softmax with mask =====================
__global__ __launch_bounds__(256) void softmax_mask(
    float* __restrict__ Sc, const int* __restrict__ mask, int mode)
{
    const int q = blockIdx.x, z = blockIdx.y;
    const int b = z >> 4;
    float* row = Sc + ((size_t)z * TT + q) * TT;
    const int tid = threadIdx.x;

    float v[4];
    float mx = -3.0e38f;
    #pragma unroll
    for (int i = 0; i < 4; i++) {
        int k = tid + i * 256;
        float s = row[k];
        int mv = (mode == 0) ? mask[q * TT + k] : mask[b * SS + k];
        v[i] = (mv == 0) ? -1e9f : s;
        mx = fmaxf(mx, v[i]);
    }

    __shared__ float red[8];
    __shared__ float red2[8];
    #pragma unroll
    for (int o = 16; o > 0; o >>= 1) mx = fmaxf(mx, __shfl_xor_sync(0xffffffffu, mx, o));
    if ((tid & 31) == 0) red[tid >> 5] = mx;
    __syncthreads();
    mx = red[0];
    #pragma unroll
    for (int w = 1; w < 8; w++) mx = fmaxf(mx, red[w]);

    float sum = 0.f;
    #pragma unroll
    for (int i = 0; i < 4; i++) { v[i] = __expf(v[i] - mx); sum += v[i]; }
    #pragma unroll
    for (int o = 16; o > 0; o >>= 1) sum += __shfl_xor_sync(0xffffffffu, sum, o);
    if ((tid & 31) == 0) red2[tid >> 5] = sum;
    __syncthreads();
    sum = 0.f;
    #pragma unroll
    for (int w = 0; w < 8; w++) sum += red2[w];
    float inv = 1.0f / sum;
    #pragma unroll
    for (int i = 0; i < 4; i++) row[tid + i * 256] = v[i] * inv;
}

// ===================== attn @ V =====================
__global__ __launch_bounds__(256) void attn_av(
    const float* __restrict__ P, const float* __restrict__ V,
    float* __restrict__ O, int causal)
{
    const int z = blockIdx.y, b = z >> 4, h = z & 15;
    const int q0 = blockIdx.x * 64;
    __shared__ float  Ps[64][65];
    __shared__ float4 Vs[64][16];
    const int tid = threadIdx.x;
    const int tx = tid & 15, ty = tid >> 4;

    float acc[4][4];
    #pragma unroll
    for (int i = 0; i < 4; i++)
        #pragma unroll
        for (int j = 0; j < 4; j++) acc[i][j] = 0.f;

    const int kend = causal ? (q0 + 64) : TT;
    for (int k0 = 0; k0 < kend; k0 += 64) {
        const float* Pb = P + ((size_t)z * TT + q0) * TT + k0;
        const float* Vb = V + ((size_t)(b * TT + k0)) * DD + h * DKD;
        #pragma unroll
        for (int it = 0; it < 4; it++) {
            int f = tid + it * 256;
            int r = f >> 4, c = (f & 15) << 2;
            float4 pv = *(const float4*)(Pb + (size_t)r * TT + c);
            Ps[r][c] = pv.x; Ps[r][c + 1] = pv.y; Ps[r][c + 2] = pv.z; Ps[r][c + 3] = pv.w;
            Vs[r][f & 15] = *(const float4*)(Vb + (size_t)r * DD + c);
        }
        __syncthreads();
        #pragma unroll
        for (int kk = 0; kk < 64; kk++) {
            float a[4];
            #pragma unroll
            for (int i = 0; i < 4; i++) a[i] = Ps[ty * 4 + i][kk];
            float4 w4 = Vs[kk][tx];
            acc[0][0] += a[0] * w4.x; acc[0][1] += a[0] * w4.y; acc[0][2] += a[0] * w4.z; acc[0][3] += a[0] * w4.w;
            acc[1][0] += a[1] * w4.x; acc[1][1] += a[1] * w4.y; acc[1][2] += a[1] * w4.z; acc[1][3] += a[1] * w4.w;
            acc[2][0] += a[2] * w4.x; acc[2][1] += a[2] * w4.y; acc[2][2] += a[2] * w4.z; acc[2][3] += a[2] * w4.w;
            acc[3][0] += a[3] * w4.x; acc[3][1] += a[3] * w4.y; acc[3][2] += a[3] * w4.z; acc[3][3] += a[3] * w4.w;
        }
        __syncthreads();
    }

    float* Ob = O + ((size_t)(b * TT + q0)) * DD + h * DKD;
    #pragma unroll
    for (int i = 0; i < 4; i++) {
        float4 o = make_float4(acc[i][0], acc[i][1], acc[i][2], acc[i][3]);
        *(float4*)(Ob + (size_t)(ty * 4 + i) * DD + tx * 4) = o;
    }
}

// ===================== residual add + LayerNorm =====================
__global__ __launch_bounds__(256) void add_ln(
    const float* __restrict__ X, const float* __restrict__ Dl,
    const float* __restrict__ g, const float* __restrict__ be,
    float* __restrict__ O)
{
    const int row = blockIdx.x;
    const float* x  = X  + (size_t)row * DD;
    const float* dl = Dl + (size_t)row * DD;
    const int tid = threadIdx.x;

    float v[4];
    float s = 0.f;
    #pragma unroll
    for (int i = 0; i < 4; i++) {
        int c = tid + i * 256;
        v[i] = x[c] + dl[c];
        s += v[i];
    }
    __shared__ float red[8];
    #pragma unroll
    for (int o = 16; o > 0; o >>= 1) s += __shfl_xor_sync(0xffffffffu, s, o);
    if ((tid & 31) == 0) red[tid >> 5] = s;
    __syncthreads();
    s = 0.f;
    #pragma unroll
    for (int w = 0; w < 8; w++) s += red[w];
    float mean = s * (1.0f / 1024.0f);

    float qq = 0.f;
    #pragma unroll
    for (int i = 0; i < 4; i++) { float d = v[i] - mean; qq += d * d; }
    __syncthreads();
    #pragma unroll
    for (int o = 16; o > 0; o >>= 1) qq += __shfl_xor_sync(0xffffffffu, qq, o);
    if ((tid & 31) == 0) red[tid >> 5] = qq;
    __syncthreads();
    qq = 0.f;
    #pragma unroll
    for (int w = 0; w < 8; w++) qq += red[w];

    float stdv = sqrtf(qq * (1.0f / 1023.0f));
    float inv = 1.0f / (stdv + LN_EPS);
    #pragma unroll
    for (int i = 0; i < 4; i++) {
        int c = tid + i * 256;
        O[(size_t)row * DD + c] = g[c] * (v[i] - mean) * inv + be[c];
    }
}

// ===================== orchestration =====================
extern "C" void kernel_launch(void* const* d_in, const int* in_sizes, int n_in,
                              void* d_out, int out_size)
{
    const float* x        = (const float*)d_in[0];
    const float* enc      = (const float*)d_in[1];
    const int*   src_mask = (const int*)  d_in[2];
    const int*   tgt_mask = (const int*)  d_in[3];
    const float* wq_s = (const float*)d_in[4],  *bq_s = (const float*)d_in[5];
    const float* wk_s = (const float*)d_in[6],  *bk_s = (const float*)d_in[7];
    const float* wv_s = (const float*)d_in[8],  *bv_s = (const float*)d_in[9];
    const float* wo_s = (const float*)d_in[10], *bo_s = (const float*)d_in[11];
    const float* wq_c = (const float*)d_in[12], *bq_c = (const float*)d_in[13];
    const float* wk_c = (const float*)d_in[14], *bk_c = (const float*)d_in[15];
    const float* wv_c = (const float*)d_in[16], *bv_c = (const float*)d_in[17];
    const float* wo_c = (const float*)d_in[18], *bo_c = (const float*)d_in[19];
    const float* w1   = (const float*)d_in[20], *b1   = (const float*)d_in[21];
    const float* w2   = (const float*)d_in[22], *b2   = (const float*)d_in[23];
    const float* g1   = (const float*)d_in[24], *be1  = (const float*)d_in[25];
    const float* g2   = (const float*)d_in[26], *be2  = (const float*)d_in[27];
    const float* g3   = (const float*)d_in[28], *be3  = (const float*)d_in[29];

    float* out     = (float*)d_out;
    float* self_w  = out + (size_t)BB * TT * DD;
    float* cross_w = self_w + (size_t)BB * HH * TT * TT;

    float *Q, *K, *V, *T0, *T1, *X1, *X2, *FF;
    __nv_bfloat16 *A3, *FF3, *WT3;
    cudaGetSymbolAddress((void**)&Q,   g_q);
    cudaGetSymbolAddress((void**)&K,   g_k);
    cudaGetSymbolAddress((void**)&V,   g_v);
    cudaGetSymbolAddress((void**)&T0,  g_t0);
    cudaGetSymbolAddress((void**)&T1,  g_t1);
    cudaGetSymbolAddress((void**)&X1,  g_x1);
    cudaGetSymbolAddress((void**)&X2,  g_x2);
    cudaGetSymbolAddress((void**)&FF,  g_ff);
    cudaGetSymbolAddress((void**)&A3,  g_a3);
    cudaGetSymbolAddress((void**)&FF3, g_ff3);
    cudaGetSymbolAddress((void**)&WT3, g_wt3);

    const int M = BB * TT;                 // 4096
    dim3 blk(256);
    dim3 tp32(32, 32);
    dim3 gD(DD / 128, M / 128);            // (8, 32)
    dim3 gF(DFFN / 128, M / 128);          // (32, 32)
    dim3 scoreG(TT / 64, TT / 64, BB * HH);
    dim3 smaxG(TT, BB * HH);
    dim3 avG(TT / 64, BB * HH);
    dim3 lnG(M);
    const int ACT_BLKS = M * DD / 4 / 256;    // 4096
    const int FF_BLKS  = M * DFFN / 4 / 256;  // 16384

    // ---- weight transpose + split (independent of data flow) ----
    split_w<<<dim3(32, 32), tp32>>>(wq_s, WT3 + 0 * W3D, DD, DD);
    split_w<<<dim3(32, 32), tp32>>>(wk_s, WT3 + 1 * W3D, DD, DD);
    split_w<<<dim3(32, 32), tp32>>>(wv_s, WT3 + 2 * W3D, DD, DD);
    split_w<<<dim3(32, 32), tp32>>>(wo_s, WT3 + 3 * W3D, DD, DD);
    split_w<<<dim3(32, 32), tp32>>>(wq_c, WT3 + 4 * W3D, DD, DD);
    split_w<<<dim3(32, 32), tp32>>>(wk_c, WT3 + 5 * W3D, DD, DD);
    split_w<<<dim3(32, 32), tp32>>>(wv_c, WT3 + 6 * W3D, DD, DD);
    split_w<<<dim3(32, 32), tp32>>>(wo_c, WT3 + 7 * W3D, DD, DD);
    split_w<<<dim3(128, 32), tp32>>>(w1, WT3 + W1OFF, DD, DFFN);
    split_w<<<dim3(32, 128), tp32>>>(w2, WT3 + W2OFF, DFFN, DD);

    // ---- self attention ----
    split_act<<<ACT_BLKS, blk>>>(x, A3, 10);
    gemm_mma<<<gD, blk>>>(A3, WT3 + 0 * W3D, bq_s, Q, DD, 3072, 0);
    gemm_mma<<<gD, blk>>>(A3, WT3 + 1 * W3D, bk_s, K, DD, 3072, 0);
    gemm_mma<<<gD, blk>>>(A3, WT3 + 2 * W3D, bv_s, V, DD, 3072, 0);
    attn_scores<<<scoreG, blk>>>(Q, K, self_w, 1);
    softmax_mask<<<smaxG, blk>>>(self_w, tgt_mask, 0);
    attn_av<<<avG, blk>>>(self_w, V, T0, 1);
    split_act<<<ACT_BLKS, blk>>>(T0, A3, 10);
    gemm_mma<<<gD, blk>>>(A3, WT3 + 3 * W3D, bo_s, T1, DD, 3072, 0);
    add_ln<<<lnG, blk>>>(x, T1, g1, be1, X1);

    // ---- cross attention ----
    split_act<<<ACT_BLKS, blk>>>(X1, A3, 10);
    gemm_mma<<<gD, blk>>>(A3, WT3 + 4 * W3D, bq_c, Q, DD, 3072, 0);
    split_act<<<ACT_BLKS, blk>>>(enc, A3, 10);
    gemm_mma<<<gD, blk>>>(A3, WT3 + 5 * W3D, bk_c, K, DD, 3072, 0);
    gemm_mma<<<gD, blk>>>(A3, WT3 + 6 * W3D, bv_c, V, DD, 3072, 0);
    attn_scores<<<scoreG, blk>>>(Q, K, cross_w, 0);
    softmax_mask<<<smaxG, blk>>>(cross_w, src_mask, 1);
    attn_av<<<avG, blk>>>(cross_w, V, T0, 0);
    split_act<<<ACT_BLKS, blk>>>(T0, A3, 10);
    gemm_mma<<<gD, blk>>>(A3, WT3 + 7 * W3D, bo_c, T1, DD, 3072, 0);
    add_ln<<<lnG, blk>>>(X1, T1, g2, be2, X2);

    // ---- feed-forward ----
    split_act<<<ACT_BLKS, blk>>>(X2, A3, 10);
    gemm_mma<<<gF, blk>>>(A3, WT3 + W1OFF, b1, FF, DFFN, 3072, 1);
    split_act<<<FF_BLKS, blk>>>(FF, FF3, 12);
    gemm_mma<<<gD, blk>>>(FF3, WT3 + W2OFF, b2, T1, DD, 12288, 0);
    add_ln<<<lnG, blk>>>(X2, T1, g3, be3, out);

    (void)in_sizes; (void)n_in; (void)out_size;
}

// round 4
// speedup vs baseline: 1.6016x; 1.0884x over previous
#include <cuda_runtime.h>
#include <cuda_bf16.h>
#include <math.h>
#include <stdint.h>

#define BB 4
#define TT 1024
#define SS 1024
#define DD 1024
#define HH 16
#define DKD 64
#define DFFN 4096
#define LN_EPS 1e-6f

// ===================== scratch (no allocations) =====================
__device__ float g_q [BB*TT*DD];
__device__ float g_k [BB*TT*DD];
__device__ float g_v [BB*TT*DD];
__device__ float g_t1[BB*TT*DD];
__device__ float g_x1[BB*TT*DD];
__device__ float g_x2[BB*TT*DD];

// bf16 split buffers
__device__ __nv_bfloat16 g_a3 [4096ULL * 3072];         // activations [M, 3K]
__device__ __nv_bfloat16 g_ff3[4096ULL * 12288];        // FF activations [M, 3*4096]
#define W3D (1024ULL*3072)
#define W1OFF (8*W3D)
#define W2OFF (8*W3D + 4096ULL*3072)
__device__ __nv_bfloat16 g_wt3[8*W3D + 4096ULL*3072 + 1024ULL*12288];

// ===================== helpers =====================
__device__ __forceinline__ uint32_t pack_hi2(float x, float y) {
    __nv_bfloat16 a = __float2bfloat16(x), b = __float2bfloat16(y);
    return (uint32_t)__bfloat16_as_ushort(a) | ((uint32_t)__bfloat16_as_ushort(b) << 16);
}
__device__ __forceinline__ uint32_t pack_lo2(float x, float y) {
    __nv_bfloat16 a = __float2bfloat16(x), b = __float2bfloat16(y);
    __nv_bfloat16 ra = __float2bfloat16(x - __bfloat162float(a));
    __nv_bfloat16 rb = __float2bfloat16(y - __bfloat162float(b));
    return (uint32_t)__bfloat16_as_ushort(ra) | ((uint32_t)__bfloat16_as_ushort(rb) << 16);
}

__device__ __forceinline__ void mma_bf16(
    float* d, const uint32_t* a, const uint32_t* b)
{
    asm volatile(
        "mma.sync.aligned.m16n8k16.row.col.f32.bf16.bf16.f32 "
        "{%0,%1,%2,%3}, {%4,%5,%6,%7}, {%8,%9}, {%0,%1,%2,%3};"
        : "+f"(d[0]), "+f"(d[1]), "+f"(d[2]), "+f"(d[3])
        : "r"(a[0]), "r"(a[1]), "r"(a[2]), "r"(a[3]), "r"(b[0]), "r"(b[1]));
}

// ===================== split/convert kernels =====================
// A [M, K=1024] fp32 -> O [M, 3K] bf16 as [hi | lo | hi]
__global__ __launch_bounds__(256) void split_act(
    const float* __restrict__ A, __nv_bfloat16* __restrict__ O)
{
    const int K = 1024;
    size_t idx = (size_t)blockIdx.x * 256 + threadIdx.x;
    size_t base = idx << 2;
    size_t m = base >> 10;
    int k = (int)(base & (size_t)(K - 1));
    float4 v = *(const float4*)(A + base);
    uint2 hh, ll;
    hh.x = pack_hi2(v.x, v.y); hh.y = pack_hi2(v.z, v.w);
    ll.x = pack_lo2(v.x, v.y); ll.y = pack_lo2(v.z, v.w);
    __nv_bfloat16* row = O + m * (size_t)(3 * K);
    *(uint2*)(row + k)         = hh;
    *(uint2*)(row + K + k)     = ll;
    *(uint2*)(row + 2 * K + k) = hh;
}

// W [K, N] fp32 -> O [N, 3K] bf16 as [hi | hi | lo] (transposed)
__global__ void split_w(
    const float* __restrict__ W, __nv_bfloat16* __restrict__ O, int K, int N)
{
    __shared__ float t[32][33];
    int k = blockIdx.y * 32 + threadIdx.y;
    int n = blockIdx.x * 32 + threadIdx.x;
    t[threadIdx.y][threadIdx.x] = W[(size_t)k * N + n];
    __syncthreads();
    int nn = blockIdx.x * 32 + threadIdx.y;
    int kk = blockIdx.y * 32 + threadIdx.x;
    float v = t[threadIdx.x][threadIdx.y];
    __nv_bfloat16 h = __float2bfloat16(v);
    __nv_bfloat16 l = __float2bfloat16(v - __bfloat162float(h));
    size_t ro = (size_t)nn * (size_t)(3 * K);
    O[ro + kk]         = h;
    O[ro + K + kk]     = h;
    O[ro + 2 * K + kk] = l;
}

// ===================== HMMA bf16 GEMM =====================
// C[M,N] = A3[M,K3] @ WT3[N,K3]^T + bias (+relu)
#define PADK 40

__global__ __launch_bounds__(256) void gemm_mma(
    const __nv_bfloat16* __restrict__ A3, const __nv_bfloat16* __restrict__ WT3,
    const float* __restrict__ bias, float* __restrict__ C,
    int N, int K3, int relu)
{
    __shared__ __nv_bfloat16 As[2][128 * PADK];
    __shared__ __nv_bfloat16 Bs[2][128 * PADK];

    const int tid = threadIdx.x;
    const int lane = tid & 31, wid = tid >> 5;
    const int wm = wid >> 2, wn = wid & 3;
    const int grp = lane >> 2, tg = lane & 3;

    const size_t arow0 = (size_t)blockIdx.y * 128;
    const size_t bcol0 = (size_t)blockIdx.x * 128;

    const int seg0 = tid, seg1 = tid + 256;
    const int r0 = seg0 >> 2, s0 = seg0 & 3;
    const int r1 = seg1 >> 2, s1 = seg1 & 3;
    const __nv_bfloat16* pA0 = A3  + (arow0 + r0) * (size_t)K3 + s0 * 8;
    const __nv_bfloat16* pA1 = A3  + (arow0 + r1) * (size_t)K3 + s1 * 8;
    const __nv_bfloat16* pB0 = WT3 + (bcol0 + r0) * (size_t)K3 + s0 * 8;
    const __nv_bfloat16* pB1 = WT3 + (bcol0 + r1) * (size_t)K3 + s1 * 8;
    const int so0 = r0 * PADK + s0 * 8;
    const int so1 = r1 * PADK + s1 * 8;

    float acc[4][4][4];
    #pragma unroll
    for (int i = 0; i < 4; i++)
        #pragma unroll
        for (int j = 0; j < 4; j++)
            #pragma unroll
            for (int q = 0; q < 4; q++) acc[i][j][q] = 0.f;

    const int NC = K3 >> 5;
    uint4 ra0 = *(const uint4*)pA0;
    uint4 ra1 = *(const uint4*)pA1;
    uint4 rb0 = *(const uint4*)pB0;
    uint4 rb1 = *(const uint4*)pB1;
    *(uint4*)&As[0][so0] = ra0;
    *(uint4*)&As[0][so1] = ra1;
    *(uint4*)&Bs[0][so0] = rb0;
    *(uint4*)&Bs[0][so1] = rb1;
    __syncthreads();

    for (int c = 0; c < NC; c++) {
        const int buf = c & 1;
        if (c + 1 < NC) {
            const size_t off = (size_t)(c + 1) * 32;
            ra0 = *(const uint4*)(pA0 + off);
            ra1 = *(const uint4*)(pA1 + off);
            rb0 = *(const uint4*)(pB0 + off);
            rb1 = *(const uint4*)(pB1 + off);
        }
        #pragma unroll
        for (int ks = 0; ks < 2; ks++) {
            const int kb = ks * 16 + tg * 2;
            uint32_t a[4][4], b[4][2];
            #pragma unroll
            for (int ms = 0; ms < 4; ms++) {
                int r = wm * 64 + ms * 16 + grp;
                a[ms][0] = *(const uint32_t*)&As[buf][r * PADK + kb];
                a[ms][1] = *(const uint32_t*)&As[buf][(r + 8) * PADK + kb];
                a[ms][2] = *(const uint32_t*)&As[buf][r * PADK + kb + 8];
                a[ms][3] = *(const uint32_t*)&As[buf][(r + 8) * PADK + kb + 8];
            }
            #pragma unroll
            for (int ns = 0; ns < 4; ns++) {
                int rn = wn * 32 + ns * 8 + grp;
                b[ns][0] = *(const uint32_t*)&Bs[buf][rn * PADK + kb];
                b[ns][1] = *(const uint32_t*)&Bs[buf][rn * PADK + kb + 8];
            }
            #pragma unroll
            for (int ms = 0; ms < 4; ms++)
                #pragma unroll
                for (int ns = 0; ns < 4; ns++)
                    mma_bf16(acc[ms][ns], a[ms], b[ns]);
        }
        if (c + 1 < NC) {
            const int nb = buf ^ 1;
            *(uint4*)&As[nb][so0] = ra0;
            *(uint4*)&As[nb][so1] = ra1;
            *(uint4*)&Bs[nb][so0] = rb0;
            *(uint4*)&Bs[nb][so1] = rb1;
        }
        __syncthreads();
    }

    #pragma unroll
    for (int ms = 0; ms < 4; ms++) {
        const size_t rr0 = arow0 + wm * 64 + ms * 16 + grp;
        #pragma unroll
        for (int ns = 0; ns < 4; ns++) {
            const size_t cc = bcol0 + wn * 32 + ns * 8 + tg * 2;
            float bx = bias[cc], by = bias[cc + 1];
            float v0 = acc[ms][ns][0] + bx;
            float v1 = acc[ms][ns][1] + by;
            float v2 = acc[ms][ns][2] + bx;
            float v3 = acc[ms][ns][3] + by;
            if (relu) {
                v0 = fmaxf(v0, 0.f); v1 = fmaxf(v1, 0.f);
                v2 = fmaxf(v2, 0.f); v3 = fmaxf(v3, 0.f);
            }
            *(float2*)(C + rr0 * N + cc)       = make_float2(v0, v1);
            *(float2*)(C + (rr0 + 8) * N + cc) = make_float2(v2, v3);
        }
    }
}

// Same GEMM but epilogue writes split bf16 [hi|lo|hi] activation layout (for FFN w1).
__global__ __launch_bounds__(256) void gemm_mma_split(
    const __nv_bfloat16* __restrict__ A3, const __nv_bfloat16* __restrict__ WT3,
    const float* __restrict__ bias, __nv_bfloat16* __restrict__ O3,
    int N, int K3)
{
    __shared__ __nv_bfloat16 As[2][128 * PADK];
    __shared__ __nv_bfloat16 Bs[2][128 * PADK];

    const int tid = threadIdx.x;
    const int lane = tid & 31, wid = tid >> 5;
    const int wm = wid >> 2, wn = wid & 3;
    const int grp = lane >> 2, tg = lane & 3;

    const size_t arow0 = (size_t)blockIdx.y * 128;
    const size_t bcol0 = (size_t)blockIdx.x * 128;

    const int seg0 = tid, seg1 = tid + 256;
    const int r0 = seg0 >> 2, s0 = seg0 & 3;
    const int r1 = seg1 >> 2, s1 = seg1 & 3;
    const __nv_bfloat16* pA0 = A3  + (arow0 + r0) * (size_t)K3 + s0 * 8;
    const __nv_bfloat16* pA1 = A3  + (arow0 + r1) * (size_t)K3 + s1 * 8;
    const __nv_bfloat16* pB0 = WT3 + (bcol0 + r0) * (size_t)K3 + s0 * 8;
    const __nv_bfloat16* pB1 = WT3 + (bcol0 + r1) * (size_t)K3 + s1 * 8;
    const int so0 = r0 * PADK + s0 * 8;
    const int so1 = r1 * PADK + s1 * 8;

    float acc[4][4][4];
    #pragma unroll
    for (int i = 0; i < 4; i++)
        #pragma unroll
        for (int j = 0; j < 4; j++)
            #pragma unroll
            for (int q = 0; q < 4; q++) acc[i][j][q] = 0.f;

    const int NC = K3 >> 5;
    uint4 ra0 = *(const uint4*)pA0;
    uint4 ra1 = *(const uint4*)pA1;
    uint4 rb0 = *(const uint4*)pB0;
    uint4 rb1 = *(const uint4*)pB1;
    *(uint4*)&As[0][so0] = ra0;
    *(uint4*)&As[0][so1] = ra1;
    *(uint4*)&Bs[0][so0] = rb0;
    *(uint4*)&Bs[0][so1] = rb1;
    __syncthreads();

    for (int c = 0; c < NC; c++) {
        const int buf = c & 1;
        if (c + 1 < NC) {
            const size_t off = (size_t)(c + 1) * 32;
            ra0 = *(const uint4*)(pA0 + off);
            ra1 = *(const uint4*)(pA1 + off);
            rb0 = *(const uint4*)(pB0 + off);
            rb1 = *(const uint4*)(pB1 + off);
        }
        #pragma unroll
        for (int ks = 0; ks < 2; ks++) {
            const int kb = ks * 16 + tg * 2;
            uint32_t a[4][4], b[4][2];
            #pragma unroll
            for (int ms = 0; ms < 4; ms++) {
                int r = wm * 64 + ms * 16 + grp;
                a[ms][0] = *(const uint32_t*)&As[buf][r * PADK + kb];
                a[ms][1] = *(const uint32_t*)&As[buf][(r + 8) * PADK + kb];
                a[ms][2] = *(const uint32_t*)&As[buf][r * PADK + kb + 8];
                a[ms][3] = *(const uint32_t*)&As[buf][(r + 8) * PADK + kb + 8];
            }
            #pragma unroll
            for (int ns = 0; ns < 4; ns++) {
                int rn = wn * 32 + ns * 8 + grp;
                b[ns][0] = *(const uint32_t*)&Bs[buf][rn * PADK + kb];
                b[ns][1] = *(const uint32_t*)&Bs[buf][rn * PADK + kb + 8];
            }
            #pragma unroll
            for (int ms = 0; ms < 4; ms++)
                #pragma unroll
                for (int ns = 0; ns < 4; ns++)
                    mma_bf16(acc[ms][ns], a[ms], b[ns]);
        }
        if (c + 1 < NC) {
            const int nb = buf ^ 1;
            *(uint4*)&As[nb][so0] = ra0;
            *(uint4*)&As[nb][so1] = ra1;
            *(uint4*)&Bs[nb][so0] = rb0;
            *(uint4*)&Bs[nb][so1] = rb1;
        }
        __syncthreads();
    }

    const size_t rstride = (size_t)3 * N;
    #pragma unroll
    for (int ms = 0; ms < 4; ms++) {
        const size_t rr0 = arow0 + wm * 64 + ms * 16 + grp;
        #pragma unroll
        for (int ns = 0; ns < 4; ns++) {
            const size_t cc = bcol0 + wn * 32 + ns * 8 + tg * 2;
            float bx = bias[cc], by = bias[cc + 1];
            float v0 = fmaxf(acc[ms][ns][0] + bx, 0.f);
            float v1 = fmaxf(acc[ms][ns][1] + by, 0.f);
            float v2 = fmaxf(acc[ms][ns][2] + bx, 0.f);
            float v3 = fmaxf(acc[ms][ns][3] + by, 0.f);
            __nv_bfloat16* R0 = O3 + rr0 * rstride;
            __nv_bfloat16* R1 = O3 + (rr0 + 8) * rstride;
            *(uint32_t*)(R0 + cc)         = pack_hi2(v0, v1);
            *(uint32_t*)(R0 + N + cc)     = pack_lo2(v0, v1);
            *(uint32_t*)(R0 + 2 * N + cc) = pack_hi2(v0, v1);
            *(uint32_t*)(R1 + cc)         = pack_hi2(v2, v3);
            *(uint32_t*)(R1 + N + cc)     = pack_lo2(v2, v3);
            *(uint32_t*)(R1 + 2 * N + cc) = pack_hi2(v2, v3);
        }
    }
}

// ===================== attention scores (HMMA, in-smem split) =====================
// S[z,q,k] = (Q_z[q,:] . K_z[k,:]) / 8; tile 128q x 64k, 8 warps (4m x 2n)
#define SPADK 200
#define SCORES_SMEM ((128 + 64) * SPADK * 2)
__global__ __launch_bounds__(256) void attn_scores_mma(
    const float* __restrict__ Q, const float* __restrict__ Kv,
    float* __restrict__ Sc, int causal)
{
    extern __shared__ __nv_bfloat16 sm[];
    __nv_bfloat16* As = sm;                 // [128][SPADK]  Q: [hi|lo|hi]
    __nv_bfloat16* Bs = sm + 128 * SPADK;   // [64][SPADK]   K: [hi|hi|lo]
    const int z = blockIdx.z, b = z >> 4, h = z & 15;
    const int q0 = blockIdx.y * 128, k0 = blockIdx.x * 64;
    if (causal && k0 >= q0 + 128) return;

    const int tid = threadIdx.x, lane = tid & 31, wid = tid >> 5;
    const int wm = wid >> 1, wn = wid & 1;
    const int grp = lane >> 2, tg = lane & 3;

    const float* Qb = Q  + ((size_t)(b * TT + q0)) * DD + h * DKD;
    const float* Kb = Kv + ((size_t)(b * TT + k0)) * DD + h * DKD;

    // load Q 128x64 (2048 float4), split into As
    #pragma unroll
    for (int i = 0; i < 8; i++) {
        int f = tid + i * 256;
        int r = f >> 4, c = (f & 15) << 2;
        float4 v = *(const float4*)(Qb + (size_t)r * DD + c);
        uint2 hh, ll;
        hh.x = pack_hi2(v.x, v.y); hh.y = pack_hi2(v.z, v.w);
        ll.x = pack_lo2(v.x, v.y); ll.y = pack_lo2(v.z, v.w);
        __nv_bfloat16* R = As + r * SPADK;
        *(uint2*)(R + c)       = hh;
        *(uint2*)(R + 64 + c)  = ll;
        *(uint2*)(R + 128 + c) = hh;
    }
    // load K 64x64 (1024 float4), split into Bs
    #pragma unroll
    for (int i = 0; i < 4; i++) {
        int f = tid + i * 256;
        int r = f >> 4, c = (f & 15) << 2;
        float4 v = *(const float4*)(Kb + (size_t)r * DD + c);
        uint2 hh, ll;
        hh.x = pack_hi2(v.x, v.y); hh.y = pack_hi2(v.z, v.w);
        ll.x = pack_lo2(v.x, v.y); ll.y = pack_lo2(v.z, v.w);
        __nv_bfloat16* R = Bs + r * SPADK;
        *(uint2*)(R + c)       = hh;
        *(uint2*)(R + 64 + c)  = hh;
        *(uint2*)(R + 128 + c) = ll;
    }
    __syncthreads();

    float acc[2][4][4];
    #pragma unroll
    for (int i = 0; i < 2; i++)
        #pragma unroll
        for (int j = 0; j < 4; j++)
            #pragma unroll
            for (int q = 0; q < 4; q++) acc[i][j][q] = 0.f;

    #pragma unroll
    for (int ks = 0; ks < 12; ks++) {
        const int kb = ks * 16 + tg * 2;
        uint32_t a[2][4], bfr[4][2];
        #pragma unroll
        for (int mi = 0; mi < 2; mi++) {
            int r = wm * 32 + mi * 16 + grp;
            a[mi][0] = *(const uint32_t*)&As[r * SPADK + kb];
            a[mi][1] = *(const uint32_t*)&As[(r + 8) * SPADK + kb];
            a[mi][2] = *(const uint32_t*)&As[r * SPADK + kb + 8];
            a[mi][3] = *(const uint32_t*)&As[(r + 8) * SPADK + kb + 8];
        }
        #pragma unroll
        for (int ni = 0; ni < 4; ni++) {
            int rn = wn * 32 + ni * 8 + grp;
            bfr[ni][0] = *(const uint32_t*)&Bs[rn * SPADK + kb];
            bfr[ni][1] = *(const uint32_t*)&Bs[rn * SPADK + kb + 8];
        }
        #pragma unroll
        for (int mi = 0; mi < 2; mi++)
            #pragma unroll
            for (int ni = 0; ni < 4; ni++)
                mma_bf16(acc[mi][ni], a[mi], bfr[ni]);
    }

    float* Out = Sc + ((size_t)z * TT + q0) * TT + k0;
    #pragma unroll
    for (int mi = 0; mi < 2; mi++) {
        const size_t r = wm * 32 + mi * 16 + grp;
        #pragma unroll
        for (int ni = 0; ni < 4; ni++) {
            const size_t c = wn * 32 + ni * 8 + tg * 2;
            *(float2*)(Out + r * TT + c) =
                make_float2(acc[mi][ni][0] * 0.125f, acc[mi][ni][1] * 0.125f);
            *(float2*)(Out + (r + 8) * TT + c) =
                make_float2(acc[mi][ni][2] * 0.125f, acc[mi][ni][3] * 0.125f);
        }
    }
}

// ===================== attn @ V (HMMA) -> writes split bf16 A3 directly =====
// O[b,q,h,:] = sum_k P[z,q,k] * V[b,k,h,:]; tile 64q x 64d, 8 warps (4m x 2n)
#define AV_SMEM ((64 + 64) * SPADK * 2)
__global__ __launch_bounds__(256) void attn_av_mma(
    const float* __restrict__ P, const float* __restrict__ V,
    __nv_bfloat16* __restrict__ A3out, int causal)
{
    extern __shared__ __nv_bfloat16 sm[];
    __nv_bfloat16* As = sm;                // [64][SPADK]  P: [hi|lo|hi]
    __nv_bfloat16* Bs = sm + 64 * SPADK;   // [64][SPADK]  V^T: [hi|hi|lo]
    const int z = blockIdx.y, b = z >> 4, h = z & 15;
    const int q0 = blockIdx.x * 64;

    const int tid = threadIdx.x, lane = tid & 31, wid = tid >> 5;
    const int wm = wid >> 1, wn = wid & 1;
    const int grp = lane >> 2, tg = lane & 3;

    float acc[4][4];
    #pragma unroll
    for (int i = 0; i < 4; i++)
        #pragma unroll
        for (int j = 0; j < 4; j++) acc[i][j] = 0.f;

    const int kend = causal ? (q0 + 64) : TT;
    for (int k0 = 0; k0 < kend; k0 += 64) {
        const float* Pb = P + ((size_t)z * TT + q0) * TT + k0;
        const float* Vb = V + ((size_t)(b * TT + k0)) * DD + h * DKD;
        #pragma unroll
        for (int i = 0; i < 4; i++) {
            int f = tid + i * 256;
            int r = f >> 4, c = (f & 15) << 2;
            // P split
            float4 pv = *(const float4*)(Pb + (size_t)r * TT + c);
            uint2 hh, ll;
            hh.x = pack_hi2(pv.x, pv.y); hh.y = pack_hi2(pv.z, pv.w);
            ll.x = pack_lo2(pv.x, pv.y); ll.y = pack_lo2(pv.z, pv.w);
            __nv_bfloat16* R = As + r * SPADK;
            *(uint2*)(R + c)       = hh;
            *(uint2*)(R + 64 + c)  = ll;
            *(uint2*)(R + 128 + c) = hh;
            // V transpose + split: Bs[d][k] with d = col of V, k = r
            float4 vv = *(const float4*)(Vb + (size_t)r * DD + c);
            float vals[4] = {vv.x, vv.y, vv.z, vv.w};
            #pragma unroll
            for (int j = 0; j < 4; j++) {
                int d = c + j;
                __nv_bfloat16 hcur = __float2bfloat16(vals[j]);
                __nv_bfloat16 lcur = __float2bfloat16(vals[j] - __bfloat162float(hcur));
                __nv_bfloat16* BR = Bs + d * SPADK;
                BR[r]       = hcur;
                BR[64 + r]  = hcur;
                BR[128 + r] = lcur;
            }
        }
        __syncthreads();
        #pragma unroll
        for (int ks = 0; ks < 12; ks++) {
            const int kb = ks * 16 + tg * 2;
            uint32_t a[4], bfr[4][2];
            int r = wm * 16 + grp;
            a[0] = *(const uint32_t*)&As[r * SPADK + kb];
            a[1] = *(const uint32_t*)&As[(r + 8) * SPADK + kb];
            a[2] = *(const uint32_t*)&As[r * SPADK + kb + 8];
            a[3] = *(const uint32_t*)&As[(r + 8) * SPADK + kb + 8];
            #pragma unroll
            for (int ni = 0; ni < 4; ni++) {
                int rn = wn * 32 + ni * 8 + grp;
                bfr[ni][0] = *(const uint32_t*)&Bs[rn * SPADK + kb];
                bfr[ni][1] = *(const uint32_t*)&Bs[rn * SPADK + kb + 8];
            }
            #pragma unroll
            for (int ni = 0; ni < 4; ni++)
                mma_bf16(acc[ni], a, bfr[ni]);
        }
        __syncthreads();
    }

    // epilogue: write [hi|lo|hi] split activation rows into A3
    const size_t m0 = (size_t)b * TT + q0 + wm * 16 + grp;
    const size_t m1 = m0 + 8;
    __nv_bfloat16* R0 = A3out + m0 * 3072;
    __nv_bfloat16* R1 = A3out + m1 * 3072;
    #pragma unroll
    for (int ni = 0; ni < 4; ni++) {
        const int cc = h * DKD + wn * 32 + ni * 8 + tg * 2;
        float v0 = acc[ni][0], v1 = acc[ni][1];
        float v2 = acc[ni][2], v3 = acc[ni][3];
        *(uint32_t*)(R0 + cc)        = pack_hi2(v0, v1);
        *(uint32_t*)(R0 + 1024 + cc) = pack_lo2(v0, v1);
        *(uint32_t*)(R0 + 2048 + cc) = pack_hi2(v0, v1);
        *(uint32_t*)(R1 + cc)        = pack_hi2(v2, v3);
        *(uint32_t*)(R1 + 1024 + cc) = pack_lo2(v2, v3);
        *(uint32_t*)(R1 + 2048 + cc) = pack_hi2(v2, v3);
    }
}

// ===================== softmax with mask =====================
__global__ __launch_bounds__(256) void softmax_mask(
    float* __restrict__ Sc, const int* __restrict__ mask, int mode)
{
    const int q = blockIdx.x, z = blockIdx.y;
    const int b = z >> 4;
    float* row = Sc + ((size_t)z * TT + q) * TT;
    const int tid = threadIdx.x;

    float v[4];
    float mx = -3.0e38f;
    #pragma unroll
    for (int i = 0; i < 4; i++) {
        int k = tid + i * 256;
        float s = row[k];
        int mv = (mode == 0) ? mask[q * TT + k] : mask[b * SS + k];
        v[i] = (mv == 0) ? -1e9f : s;
        mx = fmaxf(mx, v[i]);
    }

    __shared__ float red[8];
    __shared__ float red2[8];
    #pragma unroll
    for (int o = 16; o > 0; o >>= 1) mx = fmaxf(mx, __shfl_xor_sync(0xffffffffu, mx, o));
    if ((tid & 31) == 0) red[tid >> 5] = mx;
    __syncthreads();
    mx = red[0];
    #pragma unroll
    for (int w = 1; w < 8; w++) mx = fmaxf(mx, red[w]);

    float sum = 0.f;
    #pragma unroll
    for (int i = 0; i < 4; i++) { v[i] = __expf(v[i] - mx); sum += v[i]; }
    #pragma unroll
    for (int o = 16; o > 0; o >>= 1) sum += __shfl_xor_sync(0xffffffffu, sum, o);
    if ((tid & 31) == 0) red2[tid >> 5] = sum;
    __syncthreads();
    sum = 0.f;
    #pragma unroll
    for (int w = 0; w < 8; w++) sum += red2[w];
    float inv = 1.0f / sum;
    #pragma unroll
    for (int i = 0; i < 4; i++) row[tid + i * 256] = v[i] * inv;
}

// ===================== residual add + LayerNorm (+ optional split out) =====
__global__ __launch_bounds__(256) void add_ln(
    const float* __restrict__ X, const float* __restrict__ Dl,
    const float* __restrict__ g, const float* __restrict__ be,
    float* __restrict__ O, __nv_bfloat16* __restrict__ S3)
{
    const int row = blockIdx.x;
    const float* x  = X  + (size_t)row * DD;
    const float* dl = Dl + (size_t)row * DD;
    const int tid = threadIdx.x;

    float v[4];
    float s = 0.f;
    #pragma unroll
    for (int i = 0; i < 4; i++) {
        int c = tid + i * 256;
        v[i] = x[c] + dl[c];
        s += v[i];
    }
    __shared__ float red[8];
    #pragma unroll
    for (int o = 16; o > 0; o >>= 1) s += __shfl_xor_sync(0xffffffffu, s, o);
    if ((tid & 31) == 0) red[tid >> 5] = s;
    __syncthreads();
    s = 0.f;
    #pragma unroll
    for (int w = 0; w < 8; w++) s += red[w];
    float mean = s * (1.0f / 1024.0f);

    float qq = 0.f;
    #pragma unroll
    for (int i = 0; i < 4; i++) { float d = v[i] - mean; qq += d * d; }
    __syncthreads();
    #pragma unroll
    for (int o = 16; o > 0; o >>= 1) qq += __shfl_xor_sync(0xffffffffu, qq, o);
    if ((tid & 31) == 0) red[tid >> 5] = qq;
    __syncthreads();
    qq = 0.f;
    #pragma unroll
    for (int w = 0; w < 8; w++) qq += red[w];

    float stdv = sqrtf(qq * (1.0f / 1023.0f));
    float inv = 1.0f / (stdv + LN_EPS);
    __nv_bfloat16* R = S3 ? (S3 + (size_t)row * 3072) : (__nv_bfloat16*)0;
    #pragma unroll
    for (int i = 0; i < 4; i++) {
        int c = tid + i * 256;
        float o = g[c] * (v[i] - mean) * inv + be[c];
        O[(size_t)row * DD + c] = o;
        if (R) {
            __nv_bfloat16 h = __float2bfloat16(o);
            __nv_bfloat16 l = __float2bfloat16(o - __bfloat162float(h));
            R[c]        = h;
            R[1024 + c] = l;
            R[2048 + c] = h;
        }
    }
}

// ===================== orchestration =====================
extern "C" void kernel_launch(void* const* d_in, const int* in_sizes, int n_in,
                              void* d_out, int out_size)
{
    const float* x        = (const float*)d_in[0];
    const float* enc      = (const float*)d_in[1];
    const int*   src_mask = (const int*)  d_in[2];
    const int*   tgt_mask = (const int*)  d_in[3];
    const float* wq_s = (const float*)d_in[4],  *bq_s = (const float*)d_in[5];
    const float* wk_s = (const float*)d_in[6],  *bk_s = (const float*)d_in[7];
    const float* wv_s = (const float*)d_in[8],  *bv_s = (const float*)d_in[9];
    const float* wo_s = (const float*)d_in[10], *bo_s = (const float*)d_in[11];
    const float* wq_c = (const float*)d_in[12], *bq_c = (const float*)d_in[13];
    const float* wk_c = (const float*)d_in[14], *bk_c = (const float*)d_in[15];
    const float* wv_c = (const float*)d_in[16], *bv_c = (const float*)d_in[17];
    const float* wo_c = (const float*)d_in[18], *bo_c = (const float*)d_in[19];
    const float* w1   = (const float*)d_in[20], *b1   = (const float*)d_in[21];
    const float* w2   = (const float*)d_in[22], *b2   = (const float*)d_in[23];
    const float* g1   = (const float*)d_in[24], *be1  = (const float*)d_in[25];
    const float* g2   = (const float*)d_in[26], *be2  = (const float*)d_in[27];
    const float* g3   = (const float*)d_in[28], *be3  = (const float*)d_in[29];

    float* out     = (float*)d_out;
    float* self_w  = out + (size_t)BB * TT * DD;
    float* cross_w = self_w + (size_t)BB * HH * TT * TT;

    float *Q, *K, *V, *T1, *X1, *X2;
    __nv_bfloat16 *A3, *FF3, *WT3;
    cudaGetSymbolAddress((void**)&Q,   g_q);
    cudaGetSymbolAddress((void**)&K,   g_k);
    cudaGetSymbolAddress((void**)&V,   g_v);
    cudaGetSymbolAddress((void**)&T1,  g_t1);
    cudaGetSymbolAddress((void**)&X1,  g_x1);
    cudaGetSymbolAddress((void**)&X2,  g_x2);
    cudaGetSymbolAddress((void**)&A3,  g_a3);
    cudaGetSymbolAddress((void**)&FF3, g_ff3);
    cudaGetSymbolAddress((void**)&WT3, g_wt3);

    cudaFuncSetAttribute(attn_scores_mma, cudaFuncAttributeMaxDynamicSharedMemorySize, SCORES_SMEM);
    cudaFuncSetAttribute(attn_av_mma,     cudaFuncAttributeMaxDynamicSharedMemorySize, AV_SMEM);

    const int M = BB * TT;                 // 4096
    dim3 blk(256);
    dim3 tp32(32, 32);
    dim3 gD(DD / 128, M / 128);            // (8, 32)
    dim3 gF(DFFN / 128, M / 128);          // (32, 32)
    dim3 scoreG(TT / 64, TT / 128, BB * HH);
    dim3 smaxG(TT, BB * HH);
    dim3 avG(TT / 64, BB * HH);
    dim3 lnG(M);
    const int ACT_BLKS = M * DD / 4 / 256;    // 4096

    // ---- weight transpose + split ----
    split_w<<<dim3(32, 32), tp32>>>(wq_s, WT3 + 0 * W3D, DD, DD);
    split_w<<<dim3(32, 32), tp32>>>(wk_s, WT3 + 1 * W3D, DD, DD);
    split_w<<<dim3(32, 32), tp32>>>(wv_s, WT3 + 2 * W3D, DD, DD);
    split_w<<<dim3(32, 32), tp32>>>(wo_s, WT3 + 3 * W3D, DD, DD);
    split_w<<<dim3(32, 32), tp32>>>(wq_c, WT3 + 4 * W3D, DD, DD);
    split_w<<<dim3(32, 32), tp32>>>(wk_c, WT3 + 5 * W3D, DD, DD);
    split_w<<<dim3(32, 32), tp32>>>(wv_c, WT3 + 6 * W3D, DD, DD);
    split_w<<<dim3(32, 32), tp32>>>(wo_c, WT3 + 7 * W3D, DD, DD);
    split_w<<<dim3(128, 32), tp32>>>(w1, WT3 + W1OFF, DD, DFFN);
    split_w<<<dim3(32, 128), tp32>>>(w2, WT3 + W2OFF, DFFN, DD);

    // ---- self attention ----
    split_act<<<ACT_BLKS, blk>>>(x, A3);
    gemm_mma<<<gD, blk>>>(A3, WT3 + 0 * W3D, bq_s, Q, DD, 3072, 0);
    gemm_mma<<<gD, blk>>>(A3, WT3 + 1 * W3D, bk_s, K, DD, 3072, 0);
    gemm_mma<<<gD, blk>>>(A3, WT3 + 2 * W3D, bv_s, V, DD, 3072, 0);
    attn_scores_mma<<<scoreG, blk, SCORES_SMEM>>>(Q, K, self_w, 1);
    softmax_mask<<<smaxG, blk>>>(self_w, tgt_mask, 0);
    attn_av_mma<<<avG, blk, AV_SMEM>>>(self_w, V, A3, 1);
    gemm_mma<<<gD, blk>>>(A3, WT3 + 3 * W3D, bo_s, T1, DD, 3072, 0);
    add_ln<<<lnG, blk>>>(x, T1, g1, be1, X1, A3);

    // ---- cross attention ----
    gemm_mma<<<gD, blk>>>(A3, WT3 + 4 * W3D, bq_c, Q, DD, 3072, 0);
    split_act<<<ACT_BLKS, blk>>>(enc, A3);
    gemm_mma<<<gD, blk>>>(A3, WT3 + 5 * W3D, bk_c, K, DD, 3072, 0);
    gemm_mma<<<gD, blk>>>(A3, WT3 + 6 * W3D, bv_c, V, DD, 3072, 0);
    attn_scores_mma<<<scoreG, blk, SCORES_SMEM>>>(Q, K, cross_w, 0);
    softmax_mask<<<smaxG, blk>>>(cross_w, src_mask, 1);
    attn_av_mma<<<avG, blk, AV_SMEM>>>(cross_w, V, A3, 0);
    gemm_mma<<<gD, blk>>>(A3, WT3 + 7 * W3D, bo_c, T1, DD, 3072, 0);
    add_ln<<<lnG, blk>>>(X1, T1, g2, be2, X2, A3);

    // ---- feed-forward ----
    gemm_mma_split<<<gF, blk>>>(A3, WT3 + W1OFF, b1, FF3, DFFN, 3072);
    gemm_mma<<<gD, blk>>>(FF3, WT3 + W2OFF, b2, T1, DD, 12288, 0);
    add_ln<<<lnG, blk>>>(X2, T1, g3, be3, out, (__nv_bfloat16*)0);

    (void)in_sizes; (void)n_in; (void)out_size;
}

// round 5
// speedup vs baseline: 1.7924x; 1.1191x over previous
#include <cuda_runtime.h>
#include <cuda_bf16.h>
#include <math.h>
#include <stdint.h>

#define BB 4
#define TT 1024
#define SS 1024
#define DD 1024
#define HH 16
#define DKD 64
#define DFFN 4096
#define LN_EPS 1e-6f

// ===================== scratch (no allocations) =====================
__device__ float g_q [BB*TT*DD];
__device__ float g_k [BB*TT*DD];
__device__ float g_v [BB*TT*DD];
__device__ float g_t1[BB*TT*DD];
__device__ float g_x1[BB*TT*DD];
__device__ float g_x2[BB*TT*DD];

__device__ __nv_bfloat16 g_a3 [4096ULL * 3072];   // activations [M, 3K] (hi|lo|hi)
__device__ __nv_bfloat16 g_ff3[4096ULL * 12288];  // FF activations
__device__ __nv_bfloat16 g_vt3[4096ULL * 3072];   // V transposed+split per (b,h): [64 d][hi|hi|lo along seq]
#define W3D (1024ULL*3072)
#define W1OFF (8*W3D)
#define W2OFF (8*W3D + 4096ULL*3072)
__device__ __nv_bfloat16 g_wt3[8*W3D + 4096ULL*3072 + 1024ULL*12288];

// ===================== helpers =====================
__device__ __forceinline__ uint32_t pack_hi2(float x, float y) {
    __nv_bfloat16 a = __float2bfloat16(x), b = __float2bfloat16(y);
    return (uint32_t)__bfloat16_as_ushort(a) | ((uint32_t)__bfloat16_as_ushort(b) << 16);
}
__device__ __forceinline__ uint32_t pack_lo2(float x, float y) {
    __nv_bfloat16 a = __float2bfloat16(x), b = __float2bfloat16(y);
    __nv_bfloat16 ra = __float2bfloat16(x - __bfloat162float(a));
    __nv_bfloat16 rb = __float2bfloat16(y - __bfloat162float(b));
    return (uint32_t)__bfloat16_as_ushort(ra) | ((uint32_t)__bfloat16_as_ushort(rb) << 16);
}
__device__ __forceinline__ void mma_bf16(
    float* d, const uint32_t* a, const uint32_t* b)
{
    asm volatile(
        "mma.sync.aligned.m16n8k16.row.col.f32.bf16.bf16.f32 "
        "{%0,%1,%2,%3}, {%4,%5,%6,%7}, {%8,%9}, {%0,%1,%2,%3};"
        : "+f"(d[0]), "+f"(d[1]), "+f"(d[2]), "+f"(d[3])
        : "r"(a[0]), "r"(a[1]), "r"(a[2]), "r"(a[3]), "r"(b[0]), "r"(b[1]));
}
__device__ __forceinline__ uint32_t smem_u32(const void* p) {
    uint32_t a;
    asm("{ .reg .u64 t; cvta.to.shared.u64 t, %1; cvt.u32.u64 %0, t; }" : "=r"(a) : "l"(p));
    return a;
}
__device__ __forceinline__ void cp16(uint32_t s, const void* g) {
    asm volatile("cp.async.cg.shared.global [%0], [%1], 16;" :: "r"(s), "l"(g));
}
#define CP_COMMIT() asm volatile("cp.async.commit_group;" ::: "memory")
#define CP_WAIT2()  asm volatile("cp.async.wait_group 2;" ::: "memory")
__device__ __forceinline__ void ldm4(uint32_t& r0, uint32_t& r1, uint32_t& r2, uint32_t& r3, uint32_t a) {
    asm volatile("ldmatrix.sync.aligned.m8n8.x4.shared.b16 {%0,%1,%2,%3}, [%4];"
        : "=r"(r0), "=r"(r1), "=r"(r2), "=r"(r3) : "r"(a));
}

// ===================== split/convert kernels =====================
__global__ __launch_bounds__(256) void split_act(
    const float* __restrict__ A, __nv_bfloat16* __restrict__ O)
{
    const int K = 1024;
    size_t idx = (size_t)blockIdx.x * 256 + threadIdx.x;
    size_t base = idx << 2;
    size_t m = base >> 10;
    int k = (int)(base & (size_t)(K - 1));
    float4 v = *(const float4*)(A + base);
    uint2 hh, ll;
    hh.x = pack_hi2(v.x, v.y); hh.y = pack_hi2(v.z, v.w);
    ll.x = pack_lo2(v.x, v.y); ll.y = pack_lo2(v.z, v.w);
    __nv_bfloat16* row = O + m * (size_t)(3 * K);
    *(uint2*)(row + k)         = hh;
    *(uint2*)(row + K + k)     = ll;
    *(uint2*)(row + 2 * K + k) = hh;
}

__global__ void split_w(
    const float* __restrict__ W, __nv_bfloat16* __restrict__ O, int K, int N)
{
    __shared__ float t[32][33];
    int k = blockIdx.y * 32 + threadIdx.y;
    int n = blockIdx.x * 32 + threadIdx.x;
    t[threadIdx.y][threadIdx.x] = W[(size_t)k * N + n];
    __syncthreads();
    int nn = blockIdx.x * 32 + threadIdx.y;
    int kk = blockIdx.y * 32 + threadIdx.x;
    float v = t[threadIdx.x][threadIdx.y];
    __nv_bfloat16 h = __float2bfloat16(v);
    __nv_bfloat16 l = __float2bfloat16(v - __bfloat162float(h));
    size_t ro = (size_t)nn * (size_t)(3 * K);
    O[ro + kk]         = h;
    O[ro + K + kk]     = h;
    O[ro + 2 * K + kk] = l;
}

// V [B*T][D] fp32 -> VT3 per (b,h): [64 d][3072] bf16 as [hi|hi|lo] along seq
__global__ void vt_split(
    const float* __restrict__ V, __nv_bfloat16* __restrict__ VT3)
{
    __shared__ float t[32][33];
    const int b = blockIdx.z;
    int k = blockIdx.x * 32 + threadIdx.y;   // seq
    int d = blockIdx.y * 32 + threadIdx.x;   // feature
    t[threadIdx.y][threadIdx.x] = V[((size_t)(b * TT + k)) * DD + d];
    __syncthreads();
    int dg = blockIdx.y * 32 + threadIdx.y;
    int kg = blockIdx.x * 32 + threadIdx.x;
    float v = t[threadIdx.x][threadIdx.y];
    __nv_bfloat16 h = __float2bfloat16(v);
    __nv_bfloat16 l = __float2bfloat16(v - __bfloat162float(h));
    int hh = dg >> 6, dk = dg & 63;
    size_t row = ((size_t)(b * HH + hh) * 64 + dk) * 3072;
    VT3[row + kg]        = h;
    VT3[row + 1024 + kg] = h;
    VT3[row + 2048 + kg] = l;
}

// ===================== HMMA GEMM, cp.async pipelined =====================
#define PADK 40
#define STAGES 4
#define SSTRIDE (2 * 128 * PADK * 2)        // 20480 B per stage (A+B)
#define GEMM_SMEM (STAGES * SSTRIDE)        // 81920 B

__global__ __launch_bounds__(256) void gemm_mma(
    const __nv_bfloat16* __restrict__ A3, const __nv_bfloat16* __restrict__ WT3,
    const float* __restrict__ bias, float* __restrict__ C,
    __nv_bfloat16* __restrict__ O3, int N, int K3, int relu)
{
    extern __shared__ char dsm[];
    const uint32_t sb = smem_u32(dsm);
    const int tid = threadIdx.x;
    const int lane = tid & 31, wid = tid >> 5;
    const int wm = wid >> 2, wn = wid & 3;
    const int grp = lane >> 2, tg = lane & 3;

    const size_t arow0 = (size_t)blockIdx.y * 128;
    const size_t bcol0 = (size_t)blockIdx.x * 128;

    const int r0 = tid >> 2, s0c = (tid & 3) * 8;
    const int r1 = r0 + 64;
    const __nv_bfloat16* gA0 = A3  + (arow0 + r0) * (size_t)K3 + s0c;
    const __nv_bfloat16* gA1 = A3  + (arow0 + r1) * (size_t)K3 + s0c;
    const __nv_bfloat16* gB0 = WT3 + (bcol0 + r0) * (size_t)K3 + s0c;
    const __nv_bfloat16* gB1 = WT3 + (bcol0 + r1) * (size_t)K3 + s0c;
    const uint32_t so0 = (uint32_t)(r0 * PADK + s0c) * 2;
    const uint32_t so1 = (uint32_t)(r1 * PADK + s0c) * 2;

    const uint32_t aLM = (uint32_t)(((wm * 64) + (lane & 15)) * PADK + (lane >> 4) * 8) * 2;
    const uint32_t bLM = (uint32_t)(((wn * 32) + (lane & 15)) * PADK + (lane >> 4) * 8) * 2;

    float acc[4][4][4];
    #pragma unroll
    for (int i = 0; i < 4; i++)
        #pragma unroll
        for (int j = 0; j < 4; j++)
            #pragma unroll
            for (int q = 0; q < 4; q++) acc[i][j][q] = 0.f;

    const int NC = K3 >> 5;

    auto issue = [&](int c, int s) {
        uint32_t ab = sb + s * SSTRIDE;
        uint32_t bb = ab + 128 * PADK * 2;
        size_t off = (size_t)c * 32;
        cp16(ab + so0, gA0 + off);
        cp16(ab + so1, gA1 + off);
        cp16(bb + so0, gB0 + off);
        cp16(bb + so1, gB1 + off);
        CP_COMMIT();
    };

    issue(0, 0); issue(1, 1); issue(2, 2);

    for (int c = 0; c < NC; c++) {
        CP_WAIT2();
        __syncthreads();
        const int nxt = c + 3;
        if (nxt < NC) issue(nxt, nxt & 3); else CP_COMMIT();

        const uint32_t As0 = sb + (c & 3) * SSTRIDE;
        const uint32_t Bs0 = As0 + 128 * PADK * 2;
        #pragma unroll
        for (int ks = 0; ks < 2; ks++) {
            const uint32_t ko = ks * 32;
            uint32_t a[4][4], b[4][2];
            #pragma unroll
            for (int ms = 0; ms < 4; ms++)
                ldm4(a[ms][0], a[ms][1], a[ms][2], a[ms][3],
                     As0 + aLM + ms * (16 * PADK * 2) + ko);
            ldm4(b[0][0], b[1][0], b[0][1], b[1][1], Bs0 + bLM + ko);
            ldm4(b[2][0], b[3][0], b[2][1], b[3][1], Bs0 + bLM + 16 * PADK * 2 + ko);
            #pragma unroll
            for (int ms = 0; ms < 4; ms++)
                #pragma unroll
                for (int ns = 0; ns < 4; ns++)
                    mma_bf16(acc[ms][ns], a[ms], b[ns]);
        }
    }

    if (O3) {
        const size_t rstride = (size_t)3 * N;
        #pragma unroll
        for (int ms = 0; ms < 4; ms++) {
            const size_t rr0 = arow0 + wm * 64 + ms * 16 + grp;
            #pragma unroll
            for (int ns = 0; ns < 4; ns++) {
                const size_t cc = bcol0 + wn * 32 + ns * 8 + tg * 2;
                float bx = bias[cc], by = bias[cc + 1];
                float v0 = fmaxf(acc[ms][ns][0] + bx, 0.f);
                float v1 = fmaxf(acc[ms][ns][1] + by, 0.f);
                float v2 = fmaxf(acc[ms][ns][2] + bx, 0.f);
                float v3 = fmaxf(acc[ms][ns][3] + by, 0.f);
                __nv_bfloat16* R0 = O3 + rr0 * rstride;
                __nv_bfloat16* R1 = O3 + (rr0 + 8) * rstride;
                *(uint32_t*)(R0 + cc)         = pack_hi2(v0, v1);
                *(uint32_t*)(R0 + N + cc)     = pack_lo2(v0, v1);
                *(uint32_t*)(R0 + 2 * N + cc) = pack_hi2(v0, v1);
                *(uint32_t*)(R1 + cc)         = pack_hi2(v2, v3);
                *(uint32_t*)(R1 + N + cc)     = pack_lo2(v2, v3);
                *(uint32_t*)(R1 + 2 * N + cc) = pack_hi2(v2, v3);
            }
        }
    } else {
        #pragma unroll
        for (int ms = 0; ms < 4; ms++) {
            const size_t rr0 = arow0 + wm * 64 + ms * 16 + grp;
            #pragma unroll
            for (int ns = 0; ns < 4; ns++) {
                const size_t cc = bcol0 + wn * 32 + ns * 8 + tg * 2;
                float bx = bias[cc], by = bias[cc + 1];
                float v0 = acc[ms][ns][0] + bx;
                float v1 = acc[ms][ns][1] + by;
                float v2 = acc[ms][ns][2] + bx;
                float v3 = acc[ms][ns][3] + by;
                if (relu) {
                    v0 = fmaxf(v0, 0.f); v1 = fmaxf(v1, 0.f);
                    v2 = fmaxf(v2, 0.f); v3 = fmaxf(v3, 0.f);
                }
                *(float2*)(C + rr0 * N + cc)       = make_float2(v0, v1);
                *(float2*)(C + (rr0 + 8) * N + cc) = make_float2(v2, v3);
            }
        }
    }
}

// ===================== attention scores (HMMA + ldmatrix) =====================
#define SPADK 200
#define SCORES_SMEM ((128 + 64) * SPADK * 2)
__global__ __launch_bounds__(256) void attn_scores_mma(
    const float* __restrict__ Q, const float* __restrict__ Kv,
    float* __restrict__ Sc, int causal)
{
    extern __shared__ __nv_bfloat16 sm[];
    __nv_bfloat16* As = sm;                 // [128][SPADK]  Q: [hi|lo|hi]
    __nv_bfloat16* Bs = sm + 128 * SPADK;   // [64][SPADK]   K: [hi|hi|lo]
    const int z = blockIdx.z, b = z >> 4, h = z & 15;
    const int q0 = blockIdx.y * 128, k0 = blockIdx.x * 64;
    if (causal && k0 >= q0 + 128) return;

    const int tid = threadIdx.x, lane = tid & 31, wid = tid >> 5;
    const int wm = wid >> 1, wn = wid & 1;
    const int grp = lane >> 2, tg = lane & 3;

    const float* Qb = Q  + ((size_t)(b * TT + q0)) * DD + h * DKD;
    const float* Kb = Kv + ((size_t)(b * TT + k0)) * DD + h * DKD;

    #pragma unroll
    for (int i = 0; i < 8; i++) {
        int f = tid + i * 256;
        int r = f >> 4, c = (f & 15) << 2;
        float4 v = *(const float4*)(Qb + (size_t)r * DD + c);
        uint2 hh, ll;
        hh.x = pack_hi2(v.x, v.y); hh.y = pack_hi2(v.z, v.w);
        ll.x = pack_lo2(v.x, v.y); ll.y = pack_lo2(v.z, v.w);
        __nv_bfloat16* R = As + r * SPADK;
        *(uint2*)(R + c)       = hh;
        *(uint2*)(R + 64 + c)  = ll;
        *(uint2*)(R + 128 + c) = hh;
    }
    #pragma unroll
    for (int i = 0; i < 4; i++) {
        int f = tid + i * 256;
        int r = f >> 4, c = (f & 15) << 2;
        float4 v = *(const float4*)(Kb + (size_t)r * DD + c);
        uint2 hh, ll;
        hh.x = pack_hi2(v.x, v.y); hh.y = pack_hi2(v.z, v.w);
        ll.x = pack_lo2(v.x, v.y); ll.y = pack_lo2(v.z, v.w);
        __nv_bfloat16* R = Bs + r * SPADK;
        *(uint2*)(R + c)       = hh;
        *(uint2*)(R + 64 + c)  = hh;
        *(uint2*)(R + 128 + c) = ll;
    }
    __syncthreads();

    const uint32_t AsU = smem_u32(As), BsU = smem_u32(Bs);
    const uint32_t aLM = AsU + (uint32_t)(((wm * 32) + (lane & 15)) * SPADK + (lane >> 4) * 8) * 2;
    const uint32_t bLM = BsU + (uint32_t)(((wn * 32) + (lane & 15)) * SPADK + (lane >> 4) * 8) * 2;

    float acc[2][4][4];
    #pragma unroll
    for (int i = 0; i < 2; i++)
        #pragma unroll
        for (int j = 0; j < 4; j++)
            #pragma unroll
            for (int q = 0; q < 4; q++) acc[i][j][q] = 0.f;

    #pragma unroll
    for (int ks = 0; ks < 12; ks++) {
        const uint32_t ko = ks * 32;
        uint32_t a[2][4], bfr[4][2];
        #pragma unroll
        for (int mi = 0; mi < 2; mi++)
            ldm4(a[mi][0], a[mi][1], a[mi][2], a[mi][3],
                 aLM + mi * (16 * SPADK * 2) + ko);
        ldm4(bfr[0][0], bfr[1][0], bfr[0][1], bfr[1][1], bLM + ko);
        ldm4(bfr[2][0], bfr[3][0], bfr[2][1], bfr[3][1], bLM + 16 * SPADK * 2 + ko);
        #pragma unroll
        for (int mi = 0; mi < 2; mi++)
            #pragma unroll
            for (int ni = 0; ni < 4; ni++)
                mma_bf16(acc[mi][ni], a[mi], bfr[ni]);
    }

    float* Out = Sc + ((size_t)z * TT + q0) * TT + k0;
    #pragma unroll
    for (int mi = 0; mi < 2; mi++) {
        const size_t r = wm * 32 + mi * 16 + grp;
        #pragma unroll
        for (int ni = 0; ni < 4; ni++) {
            const size_t c = wn * 32 + ni * 8 + tg * 2;
            *(float2*)(Out + r * TT + c) =
                make_float2(acc[mi][ni][0] * 0.125f, acc[mi][ni][1] * 0.125f);
            *(float2*)(Out + (r + 8) * TT + c) =
                make_float2(acc[mi][ni][2] * 0.125f, acc[mi][ni][3] * 0.125f);
        }
    }
}

// ===================== attn @ V (HMMA + pre-transposed V) =====================
#define AV_SMEM ((64 + 64) * SPADK * 2)
__global__ __launch_bounds__(256) void attn_av_mma(
    const float* __restrict__ P, const __nv_bfloat16* __restrict__ VT3,
    __nv_bfloat16* __restrict__ A3out, int causal)
{
    extern __shared__ __nv_bfloat16 sm[];
    __nv_bfloat16* As = sm;                // [64][SPADK]  P: [hi|lo|hi]
    __nv_bfloat16* Bs = sm + 64 * SPADK;   // [64][SPADK]  V^T: [hi|hi|lo]
    const int z = blockIdx.y, b = z >> 4, h = z & 15;
    const int q0 = blockIdx.x * 64;

    const int tid = threadIdx.x, lane = tid & 31, wid = tid >> 5;
    const int wm = wid >> 1, wn = wid & 1;
    const int grp = lane >> 2, tg = lane & 3;

    const __nv_bfloat16* Vt = VT3 + (size_t)z * 64 * 3072;

    // B-copy index decomposition (1536 uint4 per tile)
    const uint32_t AsU = smem_u32(As), BsU = smem_u32(Bs);
    const uint32_t aLM = AsU + (uint32_t)(((wm * 16) + (lane & 15)) * SPADK + (lane >> 4) * 8) * 2;
    const uint32_t bLM = BsU + (uint32_t)(((wn * 32) + (lane & 15)) * SPADK + (lane >> 4) * 8) * 2;

    float acc[4][4];
    #pragma unroll
    for (int i = 0; i < 4; i++)
        #pragma unroll
        for (int j = 0; j < 4; j++) acc[i][j] = 0.f;

    const int kend = causal ? (q0 + 64) : TT;
    for (int k0 = 0; k0 < kend; k0 += 64) {
        const float* Pb = P + ((size_t)z * TT + q0) * TT + k0;
        #pragma unroll
        for (int i = 0; i < 4; i++) {
            int f = tid + i * 256;
            int r = f >> 4, c = (f & 15) << 2;
            float4 pv = *(const float4*)(Pb + (size_t)r * TT + c);
            uint2 hh, ll;
            hh.x = pack_hi2(pv.x, pv.y); hh.y = pack_hi2(pv.z, pv.w);
            ll.x = pack_lo2(pv.x, pv.y); ll.y = pack_lo2(pv.z, pv.w);
            __nv_bfloat16* R = As + r * SPADK;
            *(uint2*)(R + c)       = hh;
            *(uint2*)(R + 64 + c)  = ll;
            *(uint2*)(R + 128 + c) = hh;
        }
        #pragma unroll
        for (int i = 0; i < 6; i++) {
            int idx = tid + i * 256;
            int d = idx / 24, rem = idx - d * 24;
            int band = rem >> 3, j = rem & 7;
            uint4 v = *(const uint4*)(Vt + (size_t)d * 3072 + band * 1024 + k0 + j * 8);
            *(uint4*)(Bs + d * SPADK + band * 64 + j * 8) = v;
        }
        __syncthreads();
        #pragma unroll
        for (int ks = 0; ks < 12; ks++) {
            const uint32_t ko = ks * 32;
            uint32_t a[4], bfr[4][2];
            ldm4(a[0], a[1], a[2], a[3], aLM + ko);
            ldm4(bfr[0][0], bfr[1][0], bfr[0][1], bfr[1][1], bLM + ko);
            ldm4(bfr[2][0], bfr[3][0], bfr[2][1], bfr[3][1], bLM + 16 * SPADK * 2 + ko);
            #pragma unroll
            for (int ni = 0; ni < 4; ni++)
                mma_bf16(acc[ni], a, bfr[ni]);
        }
        __syncthreads();
    }

    const size_t m0 = (size_t)b * TT + q0 + wm * 16 + grp;
    const size_t m1 = m0 + 8;
    __nv_bfloat16* R0 = A3out + m0 * 3072;
    __nv_bfloat16* R1 = A3out + m1 * 3072;
    #pragma unroll
    for (int ni = 0; ni < 4; ni++) {
        const int cc = h * DKD + wn * 32 + ni * 8 + tg * 2;
        float v0 = acc[ni][0], v1 = acc[ni][1];
        float v2 = acc[ni][2], v3 = acc[ni][3];
        *(uint32_t*)(R0 + cc)        = pack_hi2(v0, v1);
        *(uint32_t*)(R0 + 1024 + cc) = pack_lo2(v0, v1);
        *(uint32_t*)(R0 + 2048 + cc) = pack_hi2(v0, v1);
        *(uint32_t*)(R1 + cc)        = pack_hi2(v2, v3);
        *(uint32_t*)(R1 + 1024 + cc) = pack_lo2(v2, v3);
        *(uint32_t*)(R1 + 2048 + cc) = pack_hi2(v2, v3);
    }
}

// ===================== softmax =====================
__global__ __launch_bounds__(256) void softmax_mask(
    float* __restrict__ Sc, const int* __restrict__ mask, int mode)
{
    const int q = blockIdx.x, z = blockIdx.y;
    const int b = z >> 4;
    float* row = Sc + ((size_t)z * TT + q) * TT;
    const int tid = threadIdx.x;

    float v[4];
    float mx = -3.0e38f;
    if (mode == 0) {
        const int L = q + 1;   // tril causal mask
        #pragma unroll
        for (int i = 0; i < 4; i++) {
            int k = tid + i * 256;
            if (k < L) { v[i] = row[k]; mx = fmaxf(mx, v[i]); }
            else v[i] = -1e30f;
        }
    } else {
        #pragma unroll
        for (int i = 0; i < 4; i++) {
            int k = tid + i * 256;
            float s = row[k];
            int mv = mask[b * SS + k];
            v[i] = (mv == 0) ? -1e9f : s;
            mx = fmaxf(mx, v[i]);
        }
    }

    __shared__ float red[8];
    __shared__ float red2[8];
    #pragma unroll
    for (int o = 16; o > 0; o >>= 1) mx = fmaxf(mx, __shfl_xor_sync(0xffffffffu, mx, o));
    if ((tid & 31) == 0) red[tid >> 5] = mx;
    __syncthreads();
    mx = red[0];
    #pragma unroll
    for (int w = 1; w < 8; w++) mx = fmaxf(mx, red[w]);

    float sum = 0.f;
    if (mode == 0) {
        const int L = q + 1;
        #pragma unroll
        for (int i = 0; i < 4; i++) {
            int k = tid + i * 256;
            v[i] = (k < L) ? __expf(v[i] - mx) : 0.f;
            sum += v[i];
        }
    } else {
        #pragma unroll
        for (int i = 0; i < 4; i++) { v[i] = __expf(v[i] - mx); sum += v[i]; }
    }
    #pragma unroll
    for (int o = 16; o > 0; o >>= 1) sum += __shfl_xor_sync(0xffffffffu, sum, o);
    if ((tid & 31) == 0) red2[tid >> 5] = sum;
    __syncthreads();
    sum = 0.f;
    #pragma unroll
    for (int w = 0; w < 8; w++) sum += red2[w];
    float inv = 1.0f / sum;
    #pragma unroll
    for (int i = 0; i < 4; i++) row[tid + i * 256] = v[i] * inv;
}

// ===================== residual add + LayerNorm =====================
__global__ __launch_bounds__(256) void add_ln(
    const float* __restrict__ X, const float* __restrict__ Dl,
    const float* __restrict__ g, const float* __restrict__ be,
    float* __restrict__ O, __nv_bfloat16* __restrict__ S3)
{
    const int row = blockIdx.x;
    const float* x  = X  + (size_t)row * DD;
    const float* dl = Dl + (size_t)row * DD;
    const int tid = threadIdx.x;

    float v[4];
    float s = 0.f;
    #pragma unroll
    for (int i = 0; i < 4; i++) {
        int c = tid + i * 256;
        v[i] = x[c] + dl[c];
        s += v[i];
    }
    __shared__ float red[8];
    #pragma unroll
    for (int o = 16; o > 0; o >>= 1) s += __shfl_xor_sync(0xffffffffu, s, o);
    if ((tid & 31) == 0) red[tid >> 5] = s;
    __syncthreads();
    s = 0.f;
    #pragma unroll
    for (int w = 0; w < 8; w++) s += red[w];
    float mean = s * (1.0f / 1024.0f);

    float qq = 0.f;
    #pragma unroll
    for (int i = 0; i < 4; i++) { float d = v[i] - mean; qq += d * d; }
    __syncthreads();
    #pragma unroll
    for (int o = 16; o > 0; o >>= 1) qq += __shfl_xor_sync(0xffffffffu, qq, o);
    if ((tid & 31) == 0) red[tid >> 5] = qq;
    __syncthreads();
    qq = 0.f;
    #pragma unroll
    for (int w = 0; w < 8; w++) qq += red[w];

    float stdv = sqrtf(qq * (1.0f / 1023.0f));
    float inv = 1.0f / (stdv + LN_EPS);
    __nv_bfloat16* R = S3 ? (S3 + (size_t)row * 3072) : (__nv_bfloat16*)0;
    #pragma unroll
    for (int i = 0; i < 4; i++) {
        int c = tid + i * 256;
        float o = g[c] * (v[i] - mean) * inv + be[c];
        O[(size_t)row * DD + c] = o;
        if (R) {
            __nv_bfloat16 h = __float2bfloat16(o);
            __nv_bfloat16 l = __float2bfloat16(o - __bfloat162float(h));
            R[c]        = h;
            R[1024 + c] = l;
            R[2048 + c] = h;
        }
    }
}

// ===================== orchestration =====================
extern "C" void kernel_launch(void* const* d_in, const int* in_sizes, int n_in,
                              void* d_out, int out_size)
{
    const float* x        = (const float*)d_in[0];
    const float* enc      = (const float*)d_in[1];
    const int*   src_mask = (const int*)  d_in[2];
    const float* wq_s = (const float*)d_in[4],  *bq_s = (const float*)d_in[5];
    const float* wk_s = (const float*)d_in[6],  *bk_s = (const float*)d_in[7];
    const float* wv_s = (const float*)d_in[8],  *bv_s = (const float*)d_in[9];
    const float* wo_s = (const float*)d_in[10], *bo_s = (const float*)d_in[11];
    const float* wq_c = (const float*)d_in[12], *bq_c = (const float*)d_in[13];
    const float* wk_c = (const float*)d_in[14], *bk_c = (const float*)d_in[15];
    const float* wv_c = (const float*)d_in[16], *bv_c = (const float*)d_in[17];
    const float* wo_c = (const float*)d_in[18], *bo_c = (const float*)d_in[19];
    const float* w1   = (const float*)d_in[20], *b1   = (const float*)d_in[21];
    const float* w2   = (const float*)d_in[22], *b2   = (const float*)d_in[23];
    const float* g1   = (const float*)d_in[24], *be1  = (const float*)d_in[25];
    const float* g2   = (const float*)d_in[26], *be2  = (const float*)d_in[27];
    const float* g3   = (const float*)d_in[28], *be3  = (const float*)d_in[29];

    float* out     = (float*)d_out;
    float* self_w  = out + (size_t)BB * TT * DD;
    float* cross_w = self_w + (size_t)BB * HH * TT * TT;

    float *Q, *K, *V, *T1, *X1, *X2;
    __nv_bfloat16 *A3, *FF3, *WT3, *VT3;
    cudaGetSymbolAddress((void**)&Q,   g_q);
    cudaGetSymbolAddress((void**)&K,   g_k);
    cudaGetSymbolAddress((void**)&V,   g_v);
    cudaGetSymbolAddress((void**)&T1,  g_t1);
    cudaGetSymbolAddress((void**)&X1,  g_x1);
    cudaGetSymbolAddress((void**)&X2,  g_x2);
    cudaGetSymbolAddress((void**)&A3,  g_a3);
    cudaGetSymbolAddress((void**)&FF3, g_ff3);
    cudaGetSymbolAddress((void**)&WT3, g_wt3);
    cudaGetSymbolAddress((void**)&VT3, g_vt3);

    cudaFuncSetAttribute(gemm_mma,        cudaFuncAttributeMaxDynamicSharedMemorySize, GEMM_SMEM);
    cudaFuncSetAttribute(attn_scores_mma, cudaFuncAttributeMaxDynamicSharedMemorySize, SCORES_SMEM);
    cudaFuncSetAttribute(attn_av_mma,     cudaFuncAttributeMaxDynamicSharedMemorySize, AV_SMEM);

    const int M = BB * TT;
    dim3 blk(256);
    dim3 tp32(32, 32);
    dim3 gD(DD / 128, M / 128);
    dim3 gF(DFFN / 128, M / 128);
    dim3 scoreG(TT / 64, TT / 128, BB * HH);
    dim3 smaxG(TT, BB * HH);
    dim3 avG(TT / 64, BB * HH);
    dim3 vtG(TT / 32, DD / 32, BB);
    dim3 lnG(M);
    const int ACT_BLKS = M * DD / 4 / 256;
    __nv_bfloat16* NO3 = (__nv_bfloat16*)0;

    // ---- weight transpose + split ----
    split_w<<<dim3(32, 32), tp32>>>(wq_s, WT3 + 0 * W3D, DD, DD);
    split_w<<<dim3(32, 32), tp32>>>(wk_s, WT3 + 1 * W3D, DD, DD);
    split_w<<<dim3(32, 32), tp32>>>(wv_s, WT3 + 2 * W3D, DD, DD);
    split_w<<<dim3(32, 32), tp32>>>(wo_s, WT3 + 3 * W3D, DD, DD);
    split_w<<<dim3(32, 32), tp32>>>(wq_c, WT3 + 4 * W3D, DD, DD);
    split_w<<<dim3(32, 32), tp32>>>(wk_c, WT3 + 5 * W3D, DD, DD);
    split_w<<<dim3(32, 32), tp32>>>(wv_c, WT3 + 6 * W3D, DD, DD);
    split_w<<<dim3(32, 32), tp32>>>(wo_c, WT3 + 7 * W3D, DD, DD);
    split_w<<<dim3(128, 32), tp32>>>(w1, WT3 + W1OFF, DD, DFFN);
    split_w<<<dim3(32, 128), tp32>>>(w2, WT3 + W2OFF, DFFN, DD);

    // ---- self attention ----
    split_act<<<ACT_BLKS, blk>>>(x, A3);
    gemm_mma<<<gD, blk, GEMM_SMEM>>>(A3, WT3 + 0 * W3D, bq_s, Q, NO3, DD, 3072, 0);
    gemm_mma<<<gD, blk, GEMM_SMEM>>>(A3, WT3 + 1 * W3D, bk_s, K, NO3, DD, 3072, 0);
    gemm_mma<<<gD, blk, GEMM_SMEM>>>(A3, WT3 + 2 * W3D, bv_s, V, NO3, DD, 3072, 0);
    vt_split<<<vtG, tp32>>>(V, VT3);
    attn_scores_mma<<<scoreG, blk, SCORES_SMEM>>>(Q, K, self_w, 1);
    softmax_mask<<<smaxG, blk>>>(self_w, src_mask, 0);
    attn_av_mma<<<avG, blk, AV_SMEM>>>(self_w, VT3, A3, 1);
    gemm_mma<<<gD, blk, GEMM_SMEM>>>(A3, WT3 + 3 * W3D, bo_s, T1, NO3, DD, 3072, 0);
    add_ln<<<lnG, blk>>>(x, T1, g1, be1, X1, A3);

    // ---- cross attention ----
    gemm_mma<<<gD, blk, GEMM_SMEM>>>(A3, WT3 + 4 * W3D, bq_c, Q, NO3, DD, 3072, 0);
    split_act<<<ACT_BLKS, blk>>>(enc, A3);
    gemm_mma<<<gD, blk, GEMM_SMEM>>>(A3, WT3 + 5 * W3D, bk_c, K, NO3, DD, 3072, 0);
    gemm_mma<<<gD, blk, GEMM_SMEM>>>(A3, WT3 + 6 * W3D, bv_c, V, NO3, DD, 3072, 0);
    vt_split<<<vtG, tp32>>>(V, VT3);
    attn_scores_mma<<<scoreG, blk, SCORES_SMEM>>>(Q, K, cross_w, 0);
    softmax_mask<<<smaxG, blk>>>(cross_w, src_mask, 1);
    attn_av_mma<<<avG, blk, AV_SMEM>>>(cross_w, VT3, A3, 0);
    gemm_mma<<<gD, blk, GEMM_SMEM>>>(A3, WT3 + 7 * W3D, bo_c, T1, NO3, DD, 3072, 0);
    add_ln<<<lnG, blk>>>(X1, T1, g2, be2, X2, A3);

    // ---- feed-forward ----
    gemm_mma<<<gF, blk, GEMM_SMEM>>>(A3, WT3 + W1OFF, b1, (float*)0, FF3, DFFN, 3072, 1);
    gemm_mma<<<gD, blk, GEMM_SMEM>>>(FF3, WT3 + W2OFF, b2, T1, NO3, DD, 12288, 0);
    add_ln<<<lnG, blk>>>(X2, T1, g3, be3, out, NO3);

    (void)in_sizes; (void)n_in; (void)out_size;
}